// round 1
// baseline (speedup 1.0000x reference)
#include <cuda_runtime.h>
#include <cstddef>

// ---------------------------------------------------------------------------
// learn_wavelet: 3-level learnable lifting wavelet
//   x[8,3,512,512] -> yuv -> 24 x [512,512] images
//   lift rows (h split) -> lift cols of L -> lift cols of H -> gather output
// Each lift step: H -= subnet_p(L); L += subnet_u(H)
// subnet: conv(1->16,3x3,SAME)+b, relu, conv(16->1,3x3,SAME)+b
// ---------------------------------------------------------------------------

#define NIMG 24

// Scratch buffers (device globals: allocation-free per harness rules)
__device__ float g_L [NIMG * 256 * 512];
__device__ float g_H [NIMG * 256 * 512];
__device__ float g_LL[NIMG * 256 * 256];
__device__ float g_HL[NIMG * 256 * 256];
__device__ float g_LH[NIMG * 256 * 256];
__device__ float g_HH[NIMG * 256 * 256];

// ---------------------------------------------------------------------------
// Kernel 1: RGB->YUV + even/odd row split.
// x[8,3,512,512] -> L[24,256,512] (even rows), H[24,256,512] (odd rows)
// image index = c*8 + b
// ---------------------------------------------------------------------------
__global__ void yuv_split_kernel(const float* __restrict__ x,
                                 float* __restrict__ L, float* __restrict__ H)
{
    int b   = blockIdx.y;
    int idx = blockIdx.x * 256 + threadIdx.x;      // over 512*512 plane
    int y   = idx >> 9;
    int xx  = idx & 511;

    const float* xb = x + (size_t)b * 3 * 262144;
    float r = xb[idx];
    float g = xb[262144 + idx];
    float bl = xb[2 * 262144 + idx];

    float Y =  0.299f * r + 0.587f * g + 0.114f * bl;
    float U = -0.147f * r - 0.289f * g + 0.436f * bl;
    float V =  0.615f * r - 0.515f * g - 0.100f * bl;

    float* dst = (y & 1) ? H : L;
    size_t o = (size_t)(y >> 1) * 512 + xx;
    const size_t istr = (size_t)256 * 512;
    dst[(size_t)(0 * 8 + b) * istr + o] = Y;
    dst[(size_t)(1 * 8 + b) * istr + o] = U;
    dst[(size_t)(2 * 8 + b) * istr + o] = V;
}

// ---------------------------------------------------------------------------
// Kernel 2: fused subnet + lifting update.
//   O[p] = S[p] + sign * subnet(I)[p]
// Tile: 16(h) x 32(w) outputs per 256-thread block.
// SMEM: input tile w/ halo2 (20x36) + hidden 16ch (18x34, pitch 36) + weights.
// NOTE: second conv's SAME padding zero-pads the *hidden* tensor, so hidden
// positions outside the image are forced to 0 (NOT relu(conv(zero-pad))).
// ---------------------------------------------------------------------------
__global__ void __launch_bounds__(256)
subnet_lift_kernel(const float* __restrict__ I, const float* __restrict__ S,
                   float* __restrict__ O,
                   const float* __restrict__ W1, const float* __restrict__ B1,
                   const float* __restrict__ W2, const float* __restrict__ B2,
                   float sign, int h, int w)
{
    __shared__ float sW1[144];
    __shared__ float sB1[16];
    __shared__ float sW2[144];
    __shared__ float sB2;
    __shared__ float sIn[20][37];          // rows: by-2 .. by+17 ; cols: bx-2 .. bx+33
    __shared__ float sHid[16][18 * 36];    // hidden, pitch 36 (34 used)

    const int tid = threadIdx.x;
    if (tid < 144) { sW1[tid] = W1[tid]; sW2[tid] = W2[tid]; }
    if (tid < 16)  { sB1[tid] = B1[tid]; }
    if (tid == 0)  { sB2 = B2[0]; }

    const int img = blockIdx.z;
    const int bx = blockIdx.x * 32;
    const int by = blockIdx.y * 16;
    const float* Ii = I + (size_t)img * h * w;

    // --- load input tile with halo 2, zero pad (SAME) ---
    for (int idx = tid; idx < 20 * 36; idx += 256) {
        int ly = idx / 36, lx = idx - ly * 36;
        int gy = by + ly - 2, gx = bx + lx - 2;
        float v = 0.f;
        if (gy >= 0 && gy < h && gx >= 0 && gx < w)
            v = Ii[(size_t)gy * w + gx];
        sIn[ly][lx] = v;
    }
    __syncthreads();

    // --- stage 1: conv 1->16 + relu into SMEM hidden ---
    for (int idx = tid; idx < 18 * 34; idx += 256) {
        int hy = idx / 34, hx = idx - hy * 34;
        float v[9];
#pragma unroll
        for (int dy = 0; dy < 3; dy++)
#pragma unroll
            for (int dx = 0; dx < 3; dx++)
                v[dy * 3 + dx] = sIn[hy + dy][hx + dx];

        int gy = by + hy - 1, gx = bx + hx - 1;
        bool valid = (gy >= 0 && gy < h && gx >= 0 && gx < w);
#pragma unroll
        for (int ch = 0; ch < 16; ch++) {
            float acc = sB1[ch];
#pragma unroll
            for (int k = 0; k < 9; k++)
                acc = fmaf(sW1[ch * 9 + k], v[k], acc);
            sHid[ch][hy * 36 + hx] = valid ? fmaxf(acc, 0.f) : 0.f;
        }
    }
    __syncthreads();

    // --- stage 2: conv 16->1 + lifting update. 2 output pixels per thread
    //     (same ox, rows oy and oy+8) so each weight LDS feeds 2 FMAs. ---
    const int oy = tid >> 5;      // 0..7
    const int ox = tid & 31;      // 0..31
    float acc0 = sB2, acc1 = sB2;
#pragma unroll
    for (int ch = 0; ch < 16; ch++) {
#pragma unroll
        for (int dy = 0; dy < 3; dy++) {
#pragma unroll
            for (int dx = 0; dx < 3; dx++) {
                float wv = sW2[ch * 9 + dy * 3 + dx];
                acc0 = fmaf(wv, sHid[ch][(oy + dy) * 36 + ox + dx], acc0);
                acc1 = fmaf(wv, sHid[ch][(oy + 8 + dy) * 36 + ox + dx], acc1);
            }
        }
    }

    const float* Si = S + (size_t)img * h * w;
    float* Oi = O + (size_t)img * h * w;
    int gy = by + oy, gx = bx + ox;
    size_t p0 = (size_t)gy * w + gx;
    size_t p1 = (size_t)(gy + 8) * w + gx;
    Oi[p0] = Si[p0] + sign * acc0;
    Oi[p1] = Si[p1] + sign * acc1;
}

// ---------------------------------------------------------------------------
// Kernel 3: transpose + even/odd split.
// T[24,h,w] -> E[24,w/2,h], O[24,w/2,h];  E[i,r,c]=T[i,c,2r], O[i,r,c]=T[i,c,2r+1]
// 32x32 output tiles via SMEM transpose (32 x 64 input region), conflict-free.
// ---------------------------------------------------------------------------
__global__ void transpose_split_kernel(const float* __restrict__ T,
                                       float* __restrict__ E, float* __restrict__ O,
                                       int h, int w)
{
    __shared__ float tile[32][65];
    const int img = blockIdx.z;
    const int c0 = blockIdx.x * 32;   // over h (cols of output)
    const int r0 = blockIdx.y * 32;   // over w/2 (rows of output)
    const int tx = threadIdx.x, ty = threadIdx.y;

    const float* Ti = T + (size_t)img * h * w;
#pragma unroll
    for (int k = 0; k < 4; k++) {
        int cc = ty + 8 * k;
        const float* row = Ti + (size_t)(c0 + cc) * w + 2 * r0;
        tile[cc][tx]      = row[tx];
        tile[cc][tx + 32] = row[tx + 32];
    }
    __syncthreads();

    size_t imgo = (size_t)img * (w / 2) * h;
#pragma unroll
    for (int k = 0; k < 4; k++) {
        int rr = ty + 8 * k;
        size_t o = imgo + (size_t)(r0 + rr) * h + c0 + tx;
        E[o] = tile[tx][2 * rr];
        O[o] = tile[tx][2 * rr + 1];
    }
}

// ---------------------------------------------------------------------------
// Kernel 4: gather. out[b, q*3+c, i, j] = Q_q[c*8+b, j, i]  (transpose back)
// out: [8, 12, 256, 256]. grid.z = q*24 + img.
// ---------------------------------------------------------------------------
__global__ void gather_kernel(const float* __restrict__ LL, const float* __restrict__ HL,
                              const float* __restrict__ LH, const float* __restrict__ HH,
                              float* __restrict__ out)
{
    __shared__ float tile[32][33];
    int z = blockIdx.z;
    int q = z / NIMG, img = z - q * NIMG;
    const float* Q = (q == 0) ? LL : (q == 1) ? HL : (q == 2) ? LH : HH;
    int b = img & 7, cch = img >> 3;
    int chan = q * 3 + cch;

    int i0 = blockIdx.x * 32, j0 = blockIdx.y * 32;
    int tx = threadIdx.x, ty = threadIdx.y;

    const float* Qi = Q + (size_t)img * 65536;
#pragma unroll
    for (int k = 0; k < 4; k++) {
        int jj = ty + 8 * k;
        tile[jj][tx] = Qi[(size_t)(j0 + jj) * 256 + i0 + tx];
    }
    __syncthreads();

    float* o = out + ((size_t)b * 12 + chan) * 65536;
#pragma unroll
    for (int k = 0; k < 4; k++) {
        int ii = ty + 8 * k;
        o[(size_t)(i0 + ii) * 256 + j0 + tx] = tile[tx][ii];
    }
}

// ---------------------------------------------------------------------------
extern "C" void kernel_launch(void* const* d_in, const int* in_sizes, int n_in,
                              void* d_out, int out_size)
{
    const float* x   = (const float*)d_in[0];
    const float* Wp1 = (const float*)d_in[1];
    const float* bp1 = (const float*)d_in[2];
    const float* Wp2 = (const float*)d_in[3];
    const float* bp2 = (const float*)d_in[4];
    const float* Wu1 = (const float*)d_in[5];
    const float* bu1 = (const float*)d_in[6];
    const float* Wu2 = (const float*)d_in[7];
    const float* bu2 = (const float*)d_in[8];
    float* out = (float*)d_out;

    float *pL, *pH, *pLL, *pHL, *pLH, *pHH;
    cudaGetSymbolAddress((void**)&pL,  g_L);
    cudaGetSymbolAddress((void**)&pH,  g_H);
    cudaGetSymbolAddress((void**)&pLL, g_LL);
    cudaGetSymbolAddress((void**)&pHL, g_HL);
    cudaGetSymbolAddress((void**)&pLH, g_LH);
    cudaGetSymbolAddress((void**)&pHH, g_HH);

    // 1) rgb->yuv + row split : L0[24,256,512], H0[24,256,512]
    yuv_split_kernel<<<dim3(1024, 8), 256>>>(x, pL, pH);

    // 2) lift 1 (rows): H = H - p(L); L = L + u(H)   (in-place S updates safe)
    dim3 g1(512 / 32, 256 / 16, NIMG);
    subnet_lift_kernel<<<g1, 256>>>(pL, pH, pH, Wp1, bp1, Wp2, bp2, -1.f, 256, 512);
    subnet_lift_kernel<<<g1, 256>>>(pH, pL, pL, Wu1, bu1, Wu2, bu2, +1.f, 256, 512);

    // 3) transpose + column split
    dim3 gt(256 / 32, 256 / 32, NIMG);
    transpose_split_kernel<<<gt, dim3(32, 8)>>>(pL, pLL, pHL, 256, 512);
    transpose_split_kernel<<<gt, dim3(32, 8)>>>(pH, pLH, pHH, 256, 512);

    // 4) lift 2 (L branch) and lift 3 (H branch), each [24,256,256]
    dim3 g2(256 / 32, 256 / 16, NIMG);
    subnet_lift_kernel<<<g2, 256>>>(pLL, pHL, pHL, Wp1, bp1, Wp2, bp2, -1.f, 256, 256);
    subnet_lift_kernel<<<g2, 256>>>(pHL, pLL, pLL, Wu1, bu1, Wu2, bu2, +1.f, 256, 256);
    subnet_lift_kernel<<<g2, 256>>>(pLH, pHH, pHH, Wp1, bp1, Wp2, bp2, -1.f, 256, 256);
    subnet_lift_kernel<<<g2, 256>>>(pHH, pLH, pLH, Wu1, bu1, Wu2, bu2, +1.f, 256, 256);

    // 5) transpose back + batch2channel + concat -> out [8,12,256,256]
    gather_kernel<<<dim3(8, 8, 96), dim3(32, 8)>>>(pLL, pHL, pLH, pHH, out);
}

// round 2
// speedup vs baseline: 1.5317x; 1.5317x over previous
#include <cuda_runtime.h>
#include <cstddef>

// ---------------------------------------------------------------------------
// learn_wavelet: 3-level learnable lifting wavelet
//   x[8,3,512,512] -> yuv -> 24 x [512,512] images
//   lift rows -> transpose/split -> lift cols of L, lift cols of H -> gather
// lift: H -= subnet_p(L); L += subnet_u(H)
// subnet: conv(1->16,3x3,SAME)+b, relu, conv(16->1,3x3,SAME)+b
// ---------------------------------------------------------------------------

#define NIMG 24

// Scratch (device globals: allocation-free per harness rules)
__device__ float g_L [NIMG * 256 * 512];
__device__ float g_H [NIMG * 256 * 512];
__device__ float g_LL[NIMG * 256 * 256];
__device__ float g_HL[NIMG * 256 * 256];
__device__ float g_LH[NIMG * 256 * 256];
__device__ float g_HH[NIMG * 256 * 256];

// Weights in constant memory: pset 0 = predict (p), 1 = update (u)
__constant__ float cW1[2][144];
__constant__ float cB1[2][16];
__constant__ float cW2[2][144];
__constant__ float cB2[2];

// ---------------------------------------------------------------------------
// Kernel 1: RGB->YUV + even/odd row split.
// ---------------------------------------------------------------------------
__global__ void yuv_split_kernel(const float* __restrict__ x,
                                 float* __restrict__ L, float* __restrict__ H)
{
    int b   = blockIdx.y;
    int idx = blockIdx.x * 256 + threadIdx.x;      // over 512*512 plane
    int y   = idx >> 9;
    int xx  = idx & 511;

    const float* xb = x + (size_t)b * 3 * 262144;
    float r  = xb[idx];
    float g  = xb[262144 + idx];
    float bl = xb[2 * 262144 + idx];

    float Y =  0.299f * r + 0.587f * g + 0.114f * bl;
    float U = -0.147f * r - 0.289f * g + 0.436f * bl;
    float V =  0.615f * r - 0.515f * g - 0.100f * bl;

    float* dst = (y & 1) ? H : L;
    size_t o = (size_t)(y >> 1) * 512 + xx;
    const size_t istr = (size_t)256 * 512;
    dst[(size_t)(0 * 8 + b) * istr + o] = Y;
    dst[(size_t)(1 * 8 + b) * istr + o] = U;
    dst[(size_t)(2 * 8 + b) * istr + o] = V;
}

// ---------------------------------------------------------------------------
// Kernel 2: fused subnet + lifting update.   O[p] = S[p] + sign*subnet(I)[p]
//
// Tile: 32x32 outputs, 256 threads. Hidden channels processed in 2 groups of 8
// so SMEM fits (sIn 36x37 + sHid 8x34x36 = 44.5 KB -> 5 blocks/SM).
// Stage 2: 4 px/thread (1 row x 4 cols), float2 sliding-window hidden loads,
// weights from __constant__ (uniform pipe, off the smem crossbar).
// SAME padding of conv2 zero-pads the *hidden* tensor: off-image hidden = 0.
// ---------------------------------------------------------------------------
__global__ void __launch_bounds__(256)
subnet_lift_kernel(const float* __restrict__ I, const float* __restrict__ S,
                   float* __restrict__ O, int pset, float sign, int h, int w)
{
    __shared__ float sIn[36][37];         // rows by-2..by+33, cols bx-2..bx+33
    __shared__ float sHid[8][34 * 36];    // 8 ch, 34 rows, 34 cols used (pitch 36)

    const int tid = threadIdx.x;
    const int img = blockIdx.z;
    const int bx = blockIdx.x * 32;
    const int by = blockIdx.y * 32;
    const float* Ii = I + (size_t)img * h * w;

    // --- load input tile with halo 2, zero pad (SAME) ---
    for (int idx = tid; idx < 36 * 36; idx += 256) {
        int ly = idx / 36, lx = idx - ly * 36;
        int gy = by + ly - 2, gx = bx + lx - 2;
        float v = 0.f;
        if (gy >= 0 && gy < h && gx >= 0 && gx < w)
            v = Ii[(size_t)gy * w + gx];
        sIn[ly][lx] = v;
    }
    __syncthreads();

    // stage-2 ownership: 4 consecutive px in one row
    const int oy  = tid >> 3;            // 0..31
    const int oxq = (tid & 7) * 4;       // 0,4,...,28
    float acc0 = cB2[pset], acc1 = acc0, acc2 = acc0, acc3 = acc0;

    for (int g = 0; g < 2; g++) {
        // --- stage 1: conv 1->16 (group of 8 ch) + relu -> sHid ---
        for (int idx = tid; idx < 34 * 34; idx += 256) {
            int hy = idx / 34, hx = idx - hy * 34;
            float v[9];
#pragma unroll
            for (int dy = 0; dy < 3; dy++)
#pragma unroll
                for (int dx = 0; dx < 3; dx++)
                    v[dy * 3 + dx] = sIn[hy + dy][hx + dx];

            int gy = by + hy - 1, gx = bx + hx - 1;
            bool valid = (gy >= 0 && gy < h && gx >= 0 && gx < w);
#pragma unroll
            for (int c = 0; c < 8; c++) {
                int ch = g * 8 + c;
                float acc = cB1[pset][ch];
#pragma unroll
                for (int k = 0; k < 9; k++)
                    acc = fmaf(cW1[pset][ch * 9 + k], v[k], acc);
                sHid[c][hy * 36 + hx] = valid ? fmaxf(acc, 0.f) : 0.f;
            }
        }
        __syncthreads();

        // --- stage 2 partial: conv 16->1 over this channel group ---
#pragma unroll
        for (int c = 0; c < 8; c++) {
            const float* wc = &cW2[pset][(g * 8 + c) * 9];
#pragma unroll
            for (int dy = 0; dy < 3; dy++) {
                const float2* row =
                    (const float2*)&sHid[c][(oy + dy) * 36 + oxq];
                float2 pa = row[0], pb = row[1], pc = row[2];
                float v0 = pa.x, v1 = pa.y, v2 = pb.x,
                      v3 = pb.y, v4 = pc.x, v5 = pc.y;
                float w0 = wc[dy * 3 + 0], w1 = wc[dy * 3 + 1],
                      w2 = wc[dy * 3 + 2];
                acc0 = fmaf(w0, v0, acc0); acc1 = fmaf(w0, v1, acc1);
                acc2 = fmaf(w0, v2, acc2); acc3 = fmaf(w0, v3, acc3);
                acc0 = fmaf(w1, v1, acc0); acc1 = fmaf(w1, v2, acc1);
                acc2 = fmaf(w1, v3, acc2); acc3 = fmaf(w1, v4, acc3);
                acc0 = fmaf(w2, v2, acc0); acc1 = fmaf(w2, v3, acc1);
                acc2 = fmaf(w2, v4, acc2); acc3 = fmaf(w2, v5, acc3);
            }
        }
        __syncthreads();   // before next group's stage 1 overwrites sHid
    }

    // --- epilogue: O = S + sign*acc, vectorized float4 ---
    const float* Si = S + (size_t)img * h * w;
    float* Oi = O + (size_t)img * h * w;
    size_t p = (size_t)(by + oy) * w + bx + oxq;
    float4 s = *(const float4*)(Si + p);
    float4 r;
    r.x = s.x + sign * acc0;
    r.y = s.y + sign * acc1;
    r.z = s.z + sign * acc2;
    r.w = s.w + sign * acc3;
    *(float4*)(Oi + p) = r;
}

// ---------------------------------------------------------------------------
// Kernel 3: transpose + even/odd split (L and H in one launch via grid.z).
// ---------------------------------------------------------------------------
__global__ void transpose_split_kernel(const float* __restrict__ Lsrc,
                                       const float* __restrict__ Hsrc,
                                       float* __restrict__ LLd, float* __restrict__ HLd,
                                       float* __restrict__ LHd, float* __restrict__ HHd,
                                       int h, int w)
{
    __shared__ float tile[32][65];
    int z = blockIdx.z;
    int which = z / NIMG, img = z - which * NIMG;
    const float* T = which ? Hsrc : Lsrc;
    float* E = which ? LHd : LLd;
    float* O = which ? HHd : HLd;

    const int c0 = blockIdx.x * 32;   // over h
    const int r0 = blockIdx.y * 32;   // over w/2
    const int tx = threadIdx.x, ty = threadIdx.y;

    const float* Ti = T + (size_t)img * h * w;
#pragma unroll
    for (int k = 0; k < 4; k++) {
        int cc = ty + 8 * k;
        const float* row = Ti + (size_t)(c0 + cc) * w + 2 * r0;
        tile[cc][tx]      = row[tx];
        tile[cc][tx + 32] = row[tx + 32];
    }
    __syncthreads();

    size_t imgo = (size_t)img * (w / 2) * h;
#pragma unroll
    for (int k = 0; k < 4; k++) {
        int rr = ty + 8 * k;
        size_t o = imgo + (size_t)(r0 + rr) * h + c0 + tx;
        E[o] = tile[tx][2 * rr];
        O[o] = tile[tx][2 * rr + 1];
    }
}

// ---------------------------------------------------------------------------
// Kernel 4: gather. out[b, q*3+c, i, j] = Q_q[c*8+b, j, i]
// ---------------------------------------------------------------------------
__global__ void gather_kernel(const float* __restrict__ LL, const float* __restrict__ HL,
                              const float* __restrict__ LH, const float* __restrict__ HH,
                              float* __restrict__ out)
{
    __shared__ float tile[32][33];
    int z = blockIdx.z;
    int q = z / NIMG, img = z - q * NIMG;
    const float* Q = (q == 0) ? LL : (q == 1) ? HL : (q == 2) ? LH : HH;
    int b = img & 7, cch = img >> 3;
    int chan = q * 3 + cch;

    int i0 = blockIdx.x * 32, j0 = blockIdx.y * 32;
    int tx = threadIdx.x, ty = threadIdx.y;

    const float* Qi = Q + (size_t)img * 65536;
#pragma unroll
    for (int k = 0; k < 4; k++) {
        int jj = ty + 8 * k;
        tile[jj][tx] = Qi[(size_t)(j0 + jj) * 256 + i0 + tx];
    }
    __syncthreads();

    float* o = out + ((size_t)b * 12 + chan) * 65536;
#pragma unroll
    for (int k = 0; k < 4; k++) {
        int ii = ty + 8 * k;
        o[(size_t)(i0 + ii) * 256 + j0 + tx] = tile[tx][ii];
    }
}

// ---------------------------------------------------------------------------
extern "C" void kernel_launch(void* const* d_in, const int* in_sizes, int n_in,
                              void* d_out, int out_size)
{
    const float* x   = (const float*)d_in[0];
    const float* Wp1 = (const float*)d_in[1];
    const float* bp1 = (const float*)d_in[2];
    const float* Wp2 = (const float*)d_in[3];
    const float* bp2 = (const float*)d_in[4];
    const float* Wu1 = (const float*)d_in[5];
    const float* bu1 = (const float*)d_in[6];
    const float* Wu2 = (const float*)d_in[7];
    const float* bu2 = (const float*)d_in[8];
    float* out = (float*)d_out;

    // weights -> constant memory (D2D async copies: graph-capturable)
    cudaMemcpyToSymbolAsync(cW1, Wp1, 144 * 4, 0,       cudaMemcpyDeviceToDevice);
    cudaMemcpyToSymbolAsync(cW1, Wu1, 144 * 4, 144 * 4, cudaMemcpyDeviceToDevice);
    cudaMemcpyToSymbolAsync(cB1, bp1, 16 * 4,  0,       cudaMemcpyDeviceToDevice);
    cudaMemcpyToSymbolAsync(cB1, bu1, 16 * 4,  16 * 4,  cudaMemcpyDeviceToDevice);
    cudaMemcpyToSymbolAsync(cW2, Wp2, 144 * 4, 0,       cudaMemcpyDeviceToDevice);
    cudaMemcpyToSymbolAsync(cW2, Wu2, 144 * 4, 144 * 4, cudaMemcpyDeviceToDevice);
    cudaMemcpyToSymbolAsync(cB2, bp2, 4,       0,       cudaMemcpyDeviceToDevice);
    cudaMemcpyToSymbolAsync(cB2, bu2, 4,       4,       cudaMemcpyDeviceToDevice);

    float *pL, *pH, *pLL, *pHL, *pLH, *pHH;
    cudaGetSymbolAddress((void**)&pL,  g_L);
    cudaGetSymbolAddress((void**)&pH,  g_H);
    cudaGetSymbolAddress((void**)&pLL, g_LL);
    cudaGetSymbolAddress((void**)&pHL, g_HL);
    cudaGetSymbolAddress((void**)&pLH, g_LH);
    cudaGetSymbolAddress((void**)&pHH, g_HH);

    // 1) rgb->yuv + row split
    yuv_split_kernel<<<dim3(1024, 8), 256>>>(x, pL, pH);

    // 2) lift 1 (rows), images are 256 x 512
    dim3 g1(512 / 32, 256 / 32, NIMG);
    subnet_lift_kernel<<<g1, 256>>>(pL, pH, pH, 0, -1.f, 256, 512);
    subnet_lift_kernel<<<g1, 256>>>(pH, pL, pL, 1, +1.f, 256, 512);

    // 3) transpose + column split (both branches in one launch)
    dim3 gt(256 / 32, 256 / 32, 2 * NIMG);
    transpose_split_kernel<<<gt, dim3(32, 8)>>>(pL, pH, pLL, pHL, pLH, pHH, 256, 512);

    // 4) lift 2 (L branch) and lift 3 (H branch), each 24 x 256 x 256
    dim3 g2(256 / 32, 256 / 32, NIMG);
    subnet_lift_kernel<<<g2, 256>>>(pLL, pHL, pHL, 0, -1.f, 256, 256);
    subnet_lift_kernel<<<g2, 256>>>(pHL, pLL, pLL, 1, +1.f, 256, 256);
    subnet_lift_kernel<<<g2, 256>>>(pLH, pHH, pHH, 0, -1.f, 256, 256);
    subnet_lift_kernel<<<g2, 256>>>(pHH, pLH, pLH, 1, +1.f, 256, 256);

    // 5) transpose back + batch2channel + concat -> out [8,12,256,256]
    gather_kernel<<<dim3(8, 8, 96), dim3(32, 8)>>>(pLL, pHL, pLH, pHH, out);
}

// round 3
// speedup vs baseline: 1.6649x; 1.0870x over previous
#include <cuda_runtime.h>
#include <cuda_fp16.h>
#include <cstddef>

// ---------------------------------------------------------------------------
// learn_wavelet: 3-level learnable lifting wavelet.
// Subnet kernels use packed f32x2 FMA (FFMA2) with channel-paired weights
// prepacked into __constant__, and an fp16 (half2 channel-pair) hidden tensor
// in SMEM so all 16 channels fit in one stage-1 pass.
// ---------------------------------------------------------------------------

#define NIMG 24
typedef unsigned long long ull;

// Scratch (device globals: allocation-free per harness rules)
__device__ float g_L [NIMG * 256 * 512];
__device__ float g_H [NIMG * 256 * 512];
__device__ float g_LL[NIMG * 256 * 256];
__device__ float g_HL[NIMG * 256 * 256];
__device__ float g_LH[NIMG * 256 * 256];
__device__ float g_HH[NIMG * 256 * 256];

// Channel-paired weights: pair p holds (ch 2p, ch 2p+1) in (lo, hi).
struct PackedW {
    ull   w1[2][8][9];   // [pset][pair][tap]
    ull   b1[2][8];
    ull   w2[2][8][9];
    float b2[2];
    float pad[2];
};
__device__    PackedW g_pack;
__constant__ PackedW c_pack;

// ---------------- packed f32x2 helpers ----------------
__device__ __forceinline__ ull fma2(ull a, ull b, ull c) {
    ull d; asm("fma.rn.f32x2 %0, %1, %2, %3;" : "=l"(d) : "l"(a), "l"(b), "l"(c));
    return d;
}
__device__ __forceinline__ ull dup2(float x) {
    ull d; unsigned u = __float_as_uint(x);
    asm("mov.b64 %0, {%1, %1};" : "=l"(d) : "r"(u));
    return d;
}
__device__ __forceinline__ ull pack2(float lo, float hi) {
    ull d;
    asm("mov.b64 %0, {%1, %2};" : "=l"(d)
        : "r"(__float_as_uint(lo)), "r"(__float_as_uint(hi)));
    return d;
}
__device__ __forceinline__ float2 unpack2(ull a) {
    unsigned lo, hi;
    asm("mov.b64 {%0, %1}, %2;" : "=r"(lo), "=r"(hi) : "l"(a));
    return make_float2(__uint_as_float(lo), __uint_as_float(hi));
}
// half2 (lo,hi) -> packed f32x2 (lo,hi)
__device__ __forceinline__ ull h2_to_f32x2(unsigned h) {
    ull d;
    asm("{\n\t"
        ".reg .b16 h0, h1;\n\t"
        ".reg .f32 f0, f1;\n\t"
        "mov.b32 {h0, h1}, %1;\n\t"
        "cvt.f32.f16 f0, h0;\n\t"
        "cvt.f32.f16 f1, h1;\n\t"
        "mov.b64 %0, {f0, f1};\n\t"
        "}" : "=l"(d) : "r"(h));
    return d;
}
// two f32 -> half2 bits (lo in low half)
__device__ __forceinline__ unsigned f2_to_h2(float lo, float hi) {
    unsigned r;
    asm("cvt.rn.f16x2.f32 %0, %1, %2;" : "=r"(r) : "f"(hi), "f"(lo));
    return r;
}

// ---------------------------------------------------------------------------
// Prep kernel: pack channel-paired weights into g_pack (then memcpy to const).
// ---------------------------------------------------------------------------
__global__ void prep_kernel(const float* __restrict__ Wp1, const float* __restrict__ bp1,
                            const float* __restrict__ Wp2, const float* __restrict__ bp2,
                            const float* __restrict__ Wu1, const float* __restrict__ bu1,
                            const float* __restrict__ Wu2, const float* __restrict__ bu2)
{
    int t = threadIdx.x;
    const float* W1s[2] = {Wp1, Wu1};
    const float* B1s[2] = {bp1, bu1};
    const float* W2s[2] = {Wp2, Wu2};
    const float* B2s[2] = {bp2, bu2};
    if (t < 144) {
        int ps = t / 72, r = t - ps * 72, p = r / 9, k = r - p * 9;
        *(float2*)&g_pack.w1[ps][p][k] =
            make_float2(W1s[ps][(2 * p) * 9 + k], W1s[ps][(2 * p + 1) * 9 + k]);
        *(float2*)&g_pack.w2[ps][p][k] =
            make_float2(W2s[ps][(2 * p) * 9 + k], W2s[ps][(2 * p + 1) * 9 + k]);
    }
    if (t < 16) {
        int ps = t / 8, p = t - ps * 8;
        *(float2*)&g_pack.b1[ps][p] = make_float2(B1s[ps][2 * p], B1s[ps][2 * p + 1]);
    }
    if (t < 2) g_pack.b2[t] = B2s[t][0];
}

// ---------------------------------------------------------------------------
// Kernel 1: RGB->YUV + even/odd row split.
// ---------------------------------------------------------------------------
__global__ void yuv_split_kernel(const float* __restrict__ x,
                                 float* __restrict__ L, float* __restrict__ H)
{
    int b   = blockIdx.y;
    int idx = blockIdx.x * 256 + threadIdx.x;
    int y   = idx >> 9;
    int xx  = idx & 511;

    const float* xb = x + (size_t)b * 3 * 262144;
    float r  = xb[idx];
    float g  = xb[262144 + idx];
    float bl = xb[2 * 262144 + idx];

    float Y =  0.299f * r + 0.587f * g + 0.114f * bl;
    float U = -0.147f * r - 0.289f * g + 0.436f * bl;
    float V =  0.615f * r - 0.515f * g - 0.100f * bl;

    float* dst = (y & 1) ? H : L;
    size_t o = (size_t)(y >> 1) * 512 + xx;
    const size_t istr = (size_t)256 * 512;
    dst[(size_t)(0 * 8 + b) * istr + o] = Y;
    dst[(size_t)(1 * 8 + b) * istr + o] = U;
    dst[(size_t)(2 * 8 + b) * istr + o] = V;
}

// ---------------------------------------------------------------------------
// Kernel 2: fused subnet + lift.  O[p] = S[p] + sign*subnet(I)[p]
// Tile 32x32, 256 threads. Hidden: 16 ch as 8 half2 channel-pairs, all in one
// stage-1 pass (sHid 39.2KB + sIn 5.3KB). Stage 2: 4 px/thread sliding window,
// packed f32x2 FMA, weights via __constant__ channel pairs.
// SAME padding of conv2 zero-pads the *hidden* tensor (off-image hidden = 0).
// ---------------------------------------------------------------------------
__global__ void __launch_bounds__(256, 4)
subnet_lift_kernel(const float* __restrict__ I, const float* __restrict__ S,
                   float* __restrict__ O, int pset, float sign, int h, int w)
{
    __shared__ float    sIn[36][37];        // rows by-2..by+33, cols bx-2..bx+33
    __shared__ unsigned sH[8][34 * 36];     // 8 channel-pairs (half2), pitch 36

    const int tid = threadIdx.x;
    const int img = blockIdx.z;
    const int bx = blockIdx.x * 32;
    const int by = blockIdx.y * 32;
    const float* Ii = I + (size_t)img * h * w;

    // --- load input tile with halo 2, zero pad ---
    for (int idx = tid; idx < 36 * 36; idx += 256) {
        int ly = idx / 36, lx = idx - ly * 36;
        int gy = by + ly - 2, gx = bx + lx - 2;
        float v = 0.f;
        if (gy >= 0 && gy < h && gx >= 0 && gx < w)
            v = Ii[(size_t)gy * w + gx];
        sIn[ly][lx] = v;
    }
    __syncthreads();

    // --- stage 1: conv 1->16 + relu, all 16 ch (8 packed pairs), fp16 store ---
    for (int idx = tid; idx < 34 * 34; idx += 256) {
        int hy = idx / 34, hx = idx - hy * 34;

        ull acc[8];
#pragma unroll
        for (int p = 0; p < 8; p++) acc[p] = c_pack.b1[pset][p];

#pragma unroll
        for (int k = 0; k < 9; k++) {
            int dy = k / 3, dx = k - dy * 3;
            ull vp = dup2(sIn[hy + dy][hx + dx]);
#pragma unroll
            for (int p = 0; p < 8; p++)
                acc[p] = fma2(c_pack.w1[pset][p][k], vp, acc[p]);
        }

        int gy = by + hy - 1, gx = bx + hx - 1;
        bool valid = (gy >= 0 && gy < h && gx >= 0 && gx < w);
#pragma unroll
        for (int p = 0; p < 8; p++) {
            float2 a = unpack2(acc[p]);
            float lo = valid ? fmaxf(a.x, 0.f) : 0.f;
            float hi = valid ? fmaxf(a.y, 0.f) : 0.f;
            sH[p][hy * 36 + hx] = f2_to_h2(lo, hi);
        }
    }
    __syncthreads();

    // --- stage 2: conv 16->1 + lift, 4 px/thread (row oy, cols oxq..oxq+3) ---
    const int oy  = tid >> 3;            // 0..31
    const int oxq = (tid & 7) * 4;       // 0,4,...,28

    const ull bias2 = pack2(c_pack.b2[pset], 0.f);
    ull acc0 = bias2, acc1 = bias2, acc2 = bias2, acc3 = bias2;
    // bias would be counted 4x (once per pair? no: once total) — fix: only acc init
    // NOTE: bias must be added exactly once per pixel; bias2 has b2 in lo, 0 in hi,
    // and final = lo + hi, so a single init per accumulator is exactly one b2.

#pragma unroll
    for (int p = 0; p < 8; p++) {
#pragma unroll
        for (int dy = 0; dy < 3; dy++) {
            const unsigned* row = &sH[p][(oy + dy) * 36 + oxq];
            uint4 va = *(const uint4*)row;          // elems 0..3
            uint2 vb = *(const uint2*)(row + 4);    // elems 4,5
            ull e0 = h2_to_f32x2(va.x), e1 = h2_to_f32x2(va.y);
            ull e2 = h2_to_f32x2(va.z), e3 = h2_to_f32x2(va.w);
            ull e4 = h2_to_f32x2(vb.x), e5 = h2_to_f32x2(vb.y);
            ull w0 = c_pack.w2[pset][p][dy * 3 + 0];
            ull w1 = c_pack.w2[pset][p][dy * 3 + 1];
            ull w2 = c_pack.w2[pset][p][dy * 3 + 2];
            acc0 = fma2(w0, e0, acc0); acc1 = fma2(w0, e1, acc1);
            acc2 = fma2(w0, e2, acc2); acc3 = fma2(w0, e3, acc3);
            acc0 = fma2(w1, e1, acc0); acc1 = fma2(w1, e2, acc1);
            acc2 = fma2(w1, e3, acc2); acc3 = fma2(w1, e4, acc3);
            acc0 = fma2(w2, e2, acc0); acc1 = fma2(w2, e3, acc1);
            acc2 = fma2(w2, e4, acc2); acc3 = fma2(w2, e5, acc3);
        }
    }

    float2 a0 = unpack2(acc0), a1 = unpack2(acc1),
           a2 = unpack2(acc2), a3 = unpack2(acc3);

    const float* Si = S + (size_t)img * h * w;
    float* Oi = O + (size_t)img * h * w;
    size_t pidx = (size_t)(by + oy) * w + bx + oxq;
    float4 s = *(const float4*)(Si + pidx);
    float4 r;
    r.x = s.x + sign * (a0.x + a0.y);
    r.y = s.y + sign * (a1.x + a1.y);
    r.z = s.z + sign * (a2.x + a2.y);
    r.w = s.w + sign * (a3.x + a3.y);
    *(float4*)(Oi + pidx) = r;
}

// ---------------------------------------------------------------------------
// Kernel 3: transpose + even/odd split (L and H via grid.z).
// ---------------------------------------------------------------------------
__global__ void transpose_split_kernel(const float* __restrict__ Lsrc,
                                       const float* __restrict__ Hsrc,
                                       float* __restrict__ LLd, float* __restrict__ HLd,
                                       float* __restrict__ LHd, float* __restrict__ HHd,
                                       int h, int w)
{
    __shared__ float tile[32][65];
    int z = blockIdx.z;
    int which = z / NIMG, img = z - which * NIMG;
    const float* T = which ? Hsrc : Lsrc;
    float* E = which ? LHd : LLd;
    float* O = which ? HHd : HLd;

    const int c0 = blockIdx.x * 32;
    const int r0 = blockIdx.y * 32;
    const int tx = threadIdx.x, ty = threadIdx.y;

    const float* Ti = T + (size_t)img * h * w;
#pragma unroll
    for (int k = 0; k < 4; k++) {
        int cc = ty + 8 * k;
        const float* row = Ti + (size_t)(c0 + cc) * w + 2 * r0;
        tile[cc][tx]      = row[tx];
        tile[cc][tx + 32] = row[tx + 32];
    }
    __syncthreads();

    size_t imgo = (size_t)img * (w / 2) * h;
#pragma unroll
    for (int k = 0; k < 4; k++) {
        int rr = ty + 8 * k;
        size_t o = imgo + (size_t)(r0 + rr) * h + c0 + tx;
        E[o] = tile[tx][2 * rr];
        O[o] = tile[tx][2 * rr + 1];
    }
}

// ---------------------------------------------------------------------------
// Kernel 4: gather. out[b, q*3+c, i, j] = Q_q[c*8+b, j, i]
// ---------------------------------------------------------------------------
__global__ void gather_kernel(const float* __restrict__ LL, const float* __restrict__ HL,
                              const float* __restrict__ LH, const float* __restrict__ HH,
                              float* __restrict__ out)
{
    __shared__ float tile[32][33];
    int z = blockIdx.z;
    int q = z / NIMG, img = z - q * NIMG;
    const float* Q = (q == 0) ? LL : (q == 1) ? HL : (q == 2) ? LH : HH;
    int b = img & 7, cch = img >> 3;
    int chan = q * 3 + cch;

    int i0 = blockIdx.x * 32, j0 = blockIdx.y * 32;
    int tx = threadIdx.x, ty = threadIdx.y;

    const float* Qi = Q + (size_t)img * 65536;
#pragma unroll
    for (int k = 0; k < 4; k++) {
        int jj = ty + 8 * k;
        tile[jj][tx] = Qi[(size_t)(j0 + jj) * 256 + i0 + tx];
    }
    __syncthreads();

    float* o = out + ((size_t)b * 12 + chan) * 65536;
#pragma unroll
    for (int k = 0; k < 4; k++) {
        int ii = ty + 8 * k;
        o[(size_t)(i0 + ii) * 256 + j0 + tx] = tile[tx][ii];
    }
}

// ---------------------------------------------------------------------------
extern "C" void kernel_launch(void* const* d_in, const int* in_sizes, int n_in,
                              void* d_out, int out_size)
{
    const float* x   = (const float*)d_in[0];
    const float* Wp1 = (const float*)d_in[1];
    const float* bp1 = (const float*)d_in[2];
    const float* Wp2 = (const float*)d_in[3];
    const float* bp2 = (const float*)d_in[4];
    const float* Wu1 = (const float*)d_in[5];
    const float* bu1 = (const float*)d_in[6];
    const float* Wu2 = (const float*)d_in[7];
    const float* bu2 = (const float*)d_in[8];
    float* out = (float*)d_out;

    // pack weights on device, then stage into __constant__
    prep_kernel<<<1, 256>>>(Wp1, bp1, Wp2, bp2, Wu1, bu1, Wu2, bu2);
    PackedW* pg;
    cudaGetSymbolAddress((void**)&pg, g_pack);
    cudaMemcpyToSymbolAsync(c_pack, pg, sizeof(PackedW), 0, cudaMemcpyDeviceToDevice);

    float *pL, *pH, *pLL, *pHL, *pLH, *pHH;
    cudaGetSymbolAddress((void**)&pL,  g_L);
    cudaGetSymbolAddress((void**)&pH,  g_H);
    cudaGetSymbolAddress((void**)&pLL, g_LL);
    cudaGetSymbolAddress((void**)&pHL, g_HL);
    cudaGetSymbolAddress((void**)&pLH, g_LH);
    cudaGetSymbolAddress((void**)&pHH, g_HH);

    // 1) rgb->yuv + row split
    yuv_split_kernel<<<dim3(1024, 8), 256>>>(x, pL, pH);

    // 2) lift 1 (rows), 24 x 256 x 512
    dim3 g1(512 / 32, 256 / 32, NIMG);
    subnet_lift_kernel<<<g1, 256>>>(pL, pH, pH, 0, -1.f, 256, 512);
    subnet_lift_kernel<<<g1, 256>>>(pH, pL, pL, 1, +1.f, 256, 512);

    // 3) transpose + column split
    dim3 gt(256 / 32, 256 / 32, 2 * NIMG);
    transpose_split_kernel<<<gt, dim3(32, 8)>>>(pL, pH, pLL, pHL, pLH, pHH, 256, 512);

    // 4) lift 2 (L branch) and lift 3 (H branch), each 24 x 256 x 256
    dim3 g2(256 / 32, 256 / 32, NIMG);
    subnet_lift_kernel<<<g2, 256>>>(pLL, pHL, pHL, 0, -1.f, 256, 256);
    subnet_lift_kernel<<<g2, 256>>>(pHL, pLL, pLL, 1, +1.f, 256, 256);
    subnet_lift_kernel<<<g2, 256>>>(pLH, pHH, pHH, 0, -1.f, 256, 256);
    subnet_lift_kernel<<<g2, 256>>>(pHH, pLH, pLH, 1, +1.f, 256, 256);

    // 5) transpose back + batch2channel + concat -> out [8,12,256,256]
    gather_kernel<<<dim3(8, 8, 96), dim3(32, 8)>>>(pLL, pHL, pLH, pHH, out);
}

// round 4
// speedup vs baseline: 1.8514x; 1.1120x over previous
#include <cuda_runtime.h>
#include <cstddef>

// ---------------------------------------------------------------------------
// learn_wavelet: 3-level learnable lifting wavelet.
// Subnets: packed f32x2 FMA throughout; hidden tensor stored in SMEM as fp32
// channel-pairs, 4 pairs interleaved per position (32B), XOR-swizzled for
// conflict-free LDS.128/STS.128. Two 8-channel passes keep SMEM at 44.5 KB.
// ---------------------------------------------------------------------------

#define NIMG 24
typedef unsigned long long ull;

// Scratch (device globals: allocation-free per harness rules)
__device__ float g_L [NIMG * 256 * 512];
__device__ float g_H [NIMG * 256 * 512];
__device__ float g_LL[NIMG * 256 * 256];
__device__ float g_HL[NIMG * 256 * 256];
__device__ float g_LH[NIMG * 256 * 256];
__device__ float g_HH[NIMG * 256 * 256];

// Channel-paired weights: pair p holds (ch 2p, ch 2p+1) in (lo, hi).
struct PackedW {
    ull   w1[2][8][9];   // [pset][pair][tap]
    ull   b1[2][8];
    ull   w2[2][8][9];
    float b2[2];
    float pad[2];
};
__device__   PackedW g_pack;
__constant__ PackedW c_pack;

// ---------------- packed f32x2 helpers ----------------
__device__ __forceinline__ ull fma2(ull a, ull b, ull c) {
    ull d; asm("fma.rn.f32x2 %0, %1, %2, %3;" : "=l"(d) : "l"(a), "l"(b), "l"(c));
    return d;
}
__device__ __forceinline__ ull dup2(float x) {
    ull d; unsigned u = __float_as_uint(x);
    asm("mov.b64 %0, {%1, %1};" : "=l"(d) : "r"(u));
    return d;
}
__device__ __forceinline__ ull pack2(float lo, float hi) {
    ull d;
    asm("mov.b64 %0, {%1, %2};" : "=l"(d)
        : "r"(__float_as_uint(lo)), "r"(__float_as_uint(hi)));
    return d;
}
__device__ __forceinline__ float2 unpack2(ull a) {
    unsigned lo, hi;
    asm("mov.b64 {%0, %1}, %2;" : "=r"(lo), "=r"(hi) : "l"(a));
    return make_float2(__uint_as_float(lo), __uint_as_float(hi));
}

// XOR swizzle: spread 128B-strided accesses across 16B slots (bits[7:9]->[4:6])
__device__ __forceinline__ unsigned swz(unsigned b) {
    return b ^ ((b >> 3) & 0x70);
}

// ---------------------------------------------------------------------------
// Prep kernel: pack channel-paired weights into g_pack (then memcpy to const).
// ---------------------------------------------------------------------------
__global__ void prep_kernel(const float* __restrict__ Wp1, const float* __restrict__ bp1,
                            const float* __restrict__ Wp2, const float* __restrict__ bp2,
                            const float* __restrict__ Wu1, const float* __restrict__ bu1,
                            const float* __restrict__ Wu2, const float* __restrict__ bu2)
{
    int t = threadIdx.x;
    const float* W1s[2] = {Wp1, Wu1};
    const float* B1s[2] = {bp1, bu1};
    const float* W2s[2] = {Wp2, Wu2};
    const float* B2s[2] = {bp2, bu2};
    if (t < 144) {
        int ps = t / 72, r = t - ps * 72, p = r / 9, k = r - p * 9;
        *(float2*)&g_pack.w1[ps][p][k] =
            make_float2(W1s[ps][(2 * p) * 9 + k], W1s[ps][(2 * p + 1) * 9 + k]);
        *(float2*)&g_pack.w2[ps][p][k] =
            make_float2(W2s[ps][(2 * p) * 9 + k], W2s[ps][(2 * p + 1) * 9 + k]);
    }
    if (t < 16) {
        int ps = t / 8, p = t - ps * 8;
        *(float2*)&g_pack.b1[ps][p] = make_float2(B1s[ps][2 * p], B1s[ps][2 * p + 1]);
    }
    if (t < 2) g_pack.b2[t] = B2s[t][0];
}

// ---------------------------------------------------------------------------
// Kernel 1: RGB->YUV + even/odd row split.
// ---------------------------------------------------------------------------
__global__ void yuv_split_kernel(const float* __restrict__ x,
                                 float* __restrict__ L, float* __restrict__ H)
{
    int b   = blockIdx.y;
    int idx = blockIdx.x * 256 + threadIdx.x;
    int y   = idx >> 9;
    int xx  = idx & 511;

    const float* xb = x + (size_t)b * 3 * 262144;
    float r  = xb[idx];
    float g  = xb[262144 + idx];
    float bl = xb[2 * 262144 + idx];

    float Y =  0.299f * r + 0.587f * g + 0.114f * bl;
    float U = -0.147f * r - 0.289f * g + 0.436f * bl;
    float V =  0.615f * r - 0.515f * g - 0.100f * bl;

    float* dst = (y & 1) ? H : L;
    size_t o = (size_t)(y >> 1) * 512 + xx;
    const size_t istr = (size_t)256 * 512;
    dst[(size_t)(0 * 8 + b) * istr + o] = Y;
    dst[(size_t)(1 * 8 + b) * istr + o] = U;
    dst[(size_t)(2 * 8 + b) * istr + o] = V;
}

// ---------------------------------------------------------------------------
// Kernel 2: fused subnet + lift.  O[p] = S[p] + sign*subnet(I)[p]
// Tile 32x32, 256 threads, 2 passes of 8 channels (4 pairs).
// Hidden layout: per position (row<34, col<34, pitch 36), 4 fp32 pairs = 32B,
// XOR-swizzled. Stage 2: 4 px/thread, LDS.128 = 2 f32x2 operands, no cvt.
// SAME padding of conv2 zero-pads the *hidden* tensor (off-image hidden = 0).
// ---------------------------------------------------------------------------
__global__ void __launch_bounds__(256, 4)
subnet_lift_kernel(const float* __restrict__ I, const float* __restrict__ S,
                   float* __restrict__ O, int pset, float sign, int h, int w)
{
    __shared__ float  sIn[36][37];          // rows by-2..by+33, cols bx-2..bx+33
    __shared__ float4 sH4[34 * 36 * 2];     // 34 rows x pitch 36 pos x 32B
    char* sHb = (char*)sH4;

    const int tid = threadIdx.x;
    const int img = blockIdx.z;
    const int bx = blockIdx.x * 32;
    const int by = blockIdx.y * 32;
    const float* Ii = I + (size_t)img * h * w;

    // --- load input tile with halo 2, zero pad ---
    for (int idx = tid; idx < 36 * 36; idx += 256) {
        int ly = idx / 36, lx = idx - ly * 36;
        int gy = by + ly - 2, gx = bx + lx - 2;
        float v = 0.f;
        if (gy >= 0 && gy < h && gx >= 0 && gx < w)
            v = Ii[(size_t)gy * w + gx];
        sIn[ly][lx] = v;
    }
    __syncthreads();

    // stage-2 ownership: 4 consecutive px in row oy
    const int oy  = tid >> 3;            // 0..31
    const int oxq = (tid & 7) * 4;       // 0,4,...,28

    ull acc0 = pack2(c_pack.b2[pset], 0.f);   // bias once per px (lo), hi=0
    ull acc1 = acc0, acc2 = acc0, acc3 = acc0;

    for (int g = 0; g < 2; g++) {
        // --- stage 1: conv 1->8 (pairs 4g..4g+3) + relu -> packed SMEM ---
        for (int idx = tid; idx < 34 * 34; idx += 256) {
            int hy = idx / 34, hx = idx - hy * 34;

            ull a0 = c_pack.b1[pset][4 * g + 0];
            ull a1 = c_pack.b1[pset][4 * g + 1];
            ull a2 = c_pack.b1[pset][4 * g + 2];
            ull a3 = c_pack.b1[pset][4 * g + 3];
#pragma unroll
            for (int k = 0; k < 9; k++) {
                int dy = k / 3, dx = k - dy * 3;
                ull vp = dup2(sIn[hy + dy][hx + dx]);
                a0 = fma2(c_pack.w1[pset][4 * g + 0][k], vp, a0);
                a1 = fma2(c_pack.w1[pset][4 * g + 1][k], vp, a1);
                a2 = fma2(c_pack.w1[pset][4 * g + 2][k], vp, a2);
                a3 = fma2(c_pack.w1[pset][4 * g + 3][k], vp, a3);
            }

            int gy = by + hy - 1, gx = bx + hx - 1;
            bool valid = (gy >= 0 && gy < h && gx >= 0 && gx < w);
            float2 f0 = unpack2(a0), f1 = unpack2(a1),
                   f2 = unpack2(a2), f3 = unpack2(a3);
            float4 v0, v1;
            v0.x = valid ? fmaxf(f0.x, 0.f) : 0.f;
            v0.y = valid ? fmaxf(f0.y, 0.f) : 0.f;
            v0.z = valid ? fmaxf(f1.x, 0.f) : 0.f;
            v0.w = valid ? fmaxf(f1.y, 0.f) : 0.f;
            v1.x = valid ? fmaxf(f2.x, 0.f) : 0.f;
            v1.y = valid ? fmaxf(f2.y, 0.f) : 0.f;
            v1.z = valid ? fmaxf(f3.x, 0.f) : 0.f;
            v1.w = valid ? fmaxf(f3.y, 0.f) : 0.f;

            unsigned b0 = (unsigned)(hy * 36 + hx) * 32;
            *(float4*)(sHb + swz(b0))      = v0;   // pairs 4g, 4g+1
            *(float4*)(sHb + swz(b0 + 16)) = v1;   // pairs 4g+2, 4g+3
        }
        __syncthreads();

        // --- stage 2 partial: conv 8->1 over this group's 4 pairs ---
#pragma unroll
        for (int ck = 0; ck < 2; ck++) {
            const int pr = 4 * g + 2 * ck;        // pairs pr (A), pr+1 (B)
            const ull* wA = c_pack.w2[pset][pr];
            const ull* wB = c_pack.w2[pset][pr + 1];
#pragma unroll
            for (int dy = 0; dy < 3; dy++) {
                unsigned base = (unsigned)((oy + dy) * 36 + oxq) * 32 + ck * 16;
                ull A[6], B[6];
#pragma unroll
                for (int j = 0; j < 6; j++) {
                    ulonglong2 v =
                        *(const ulonglong2*)(sHb + swz(base + j * 32));
                    A[j] = v.x; B[j] = v.y;
                }
#pragma unroll
                for (int t = 0; t < 3; t++) {
                    ull wa = wA[dy * 3 + t], wb = wB[dy * 3 + t];
                    acc0 = fma2(wa, A[0 + t], acc0);
                    acc1 = fma2(wa, A[1 + t], acc1);
                    acc2 = fma2(wa, A[2 + t], acc2);
                    acc3 = fma2(wa, A[3 + t], acc3);
                    acc0 = fma2(wb, B[0 + t], acc0);
                    acc1 = fma2(wb, B[1 + t], acc1);
                    acc2 = fma2(wb, B[2 + t], acc2);
                    acc3 = fma2(wb, B[3 + t], acc3);
                }
            }
        }
        if (g == 0) __syncthreads();   // before next pass overwrites sH
    }

    float2 a0 = unpack2(acc0), a1 = unpack2(acc1),
           a2 = unpack2(acc2), a3 = unpack2(acc3);

    const float* Si = S + (size_t)img * h * w;
    float* Oi = O + (size_t)img * h * w;
    size_t pidx = (size_t)(by + oy) * w + bx + oxq;
    float4 s = *(const float4*)(Si + pidx);
    float4 r;
    r.x = s.x + sign * (a0.x + a0.y);
    r.y = s.y + sign * (a1.x + a1.y);
    r.z = s.z + sign * (a2.x + a2.y);
    r.w = s.w + sign * (a3.x + a3.y);
    *(float4*)(Oi + pidx) = r;
}

// ---------------------------------------------------------------------------
// Kernel 3: transpose + even/odd split (L and H via grid.z).
// ---------------------------------------------------------------------------
__global__ void transpose_split_kernel(const float* __restrict__ Lsrc,
                                       const float* __restrict__ Hsrc,
                                       float* __restrict__ LLd, float* __restrict__ HLd,
                                       float* __restrict__ LHd, float* __restrict__ HHd,
                                       int h, int w)
{
    __shared__ float tile[32][65];
    int z = blockIdx.z;
    int which = z / NIMG, img = z - which * NIMG;
    const float* T = which ? Hsrc : Lsrc;
    float* E = which ? LHd : LLd;
    float* O = which ? HHd : HLd;

    const int c0 = blockIdx.x * 32;
    const int r0 = blockIdx.y * 32;
    const int tx = threadIdx.x, ty = threadIdx.y;

    const float* Ti = T + (size_t)img * h * w;
#pragma unroll
    for (int k = 0; k < 4; k++) {
        int cc = ty + 8 * k;
        const float* row = Ti + (size_t)(c0 + cc) * w + 2 * r0;
        tile[cc][tx]      = row[tx];
        tile[cc][tx + 32] = row[tx + 32];
    }
    __syncthreads();

    size_t imgo = (size_t)img * (w / 2) * h;
#pragma unroll
    for (int k = 0; k < 4; k++) {
        int rr = ty + 8 * k;
        size_t o = imgo + (size_t)(r0 + rr) * h + c0 + tx;
        E[o] = tile[tx][2 * rr];
        O[o] = tile[tx][2 * rr + 1];
    }
}

// ---------------------------------------------------------------------------
// Kernel 4: gather. out[b, q*3+c, i, j] = Q_q[c*8+b, j, i]
// ---------------------------------------------------------------------------
__global__ void gather_kernel(const float* __restrict__ LL, const float* __restrict__ HL,
                              const float* __restrict__ LH, const float* __restrict__ HH,
                              float* __restrict__ out)
{
    __shared__ float tile[32][33];
    int z = blockIdx.z;
    int q = z / NIMG, img = z - q * NIMG;
    const float* Q = (q == 0) ? LL : (q == 1) ? HL : (q == 2) ? LH : HH;
    int b = img & 7, cch = img >> 3;
    int chan = q * 3 + cch;

    int i0 = blockIdx.x * 32, j0 = blockIdx.y * 32;
    int tx = threadIdx.x, ty = threadIdx.y;

    const float* Qi = Q + (size_t)img * 65536;
#pragma unroll
    for (int k = 0; k < 4; k++) {
        int jj = ty + 8 * k;
        tile[jj][tx] = Qi[(size_t)(j0 + jj) * 256 + i0 + tx];
    }
    __syncthreads();

    float* o = out + ((size_t)b * 12 + chan) * 65536;
#pragma unroll
    for (int k = 0; k < 4; k++) {
        int ii = ty + 8 * k;
        o[(size_t)(i0 + ii) * 256 + j0 + tx] = tile[tx][ii];
    }
}

// ---------------------------------------------------------------------------
extern "C" void kernel_launch(void* const* d_in, const int* in_sizes, int n_in,
                              void* d_out, int out_size)
{
    const float* x   = (const float*)d_in[0];
    const float* Wp1 = (const float*)d_in[1];
    const float* bp1 = (const float*)d_in[2];
    const float* Wp2 = (const float*)d_in[3];
    const float* bp2 = (const float*)d_in[4];
    const float* Wu1 = (const float*)d_in[5];
    const float* bu1 = (const float*)d_in[6];
    const float* Wu2 = (const float*)d_in[7];
    const float* bu2 = (const float*)d_in[8];
    float* out = (float*)d_out;

    // pack weights on device, then stage into __constant__
    prep_kernel<<<1, 256>>>(Wp1, bp1, Wp2, bp2, Wu1, bu1, Wu2, bu2);
    PackedW* pg;
    cudaGetSymbolAddress((void**)&pg, g_pack);
    cudaMemcpyToSymbolAsync(c_pack, pg, sizeof(PackedW), 0, cudaMemcpyDeviceToDevice);

    float *pL, *pH, *pLL, *pHL, *pLH, *pHH;
    cudaGetSymbolAddress((void**)&pL,  g_L);
    cudaGetSymbolAddress((void**)&pH,  g_H);
    cudaGetSymbolAddress((void**)&pLL, g_LL);
    cudaGetSymbolAddress((void**)&pHL, g_HL);
    cudaGetSymbolAddress((void**)&pLH, g_LH);
    cudaGetSymbolAddress((void**)&pHH, g_HH);

    // 1) rgb->yuv + row split
    yuv_split_kernel<<<dim3(1024, 8), 256>>>(x, pL, pH);

    // 2) lift 1 (rows), 24 x 256 x 512
    dim3 g1(512 / 32, 256 / 32, NIMG);
    subnet_lift_kernel<<<g1, 256>>>(pL, pH, pH, 0, -1.f, 256, 512);
    subnet_lift_kernel<<<g1, 256>>>(pH, pL, pL, 1, +1.f, 256, 512);

    // 3) transpose + column split
    dim3 gt(256 / 32, 256 / 32, 2 * NIMG);
    transpose_split_kernel<<<gt, dim3(32, 8)>>>(pL, pH, pLL, pHL, pLH, pHH, 256, 512);

    // 4) lift 2 (L branch) and lift 3 (H branch), each 24 x 256 x 256
    dim3 g2(256 / 32, 256 / 32, NIMG);
    subnet_lift_kernel<<<g2, 256>>>(pLL, pHL, pHL, 0, -1.f, 256, 256);
    subnet_lift_kernel<<<g2, 256>>>(pHL, pLL, pLL, 1, +1.f, 256, 256);
    subnet_lift_kernel<<<g2, 256>>>(pLH, pHH, pHH, 0, -1.f, 256, 256);
    subnet_lift_kernel<<<g2, 256>>>(pHH, pLH, pLH, 1, +1.f, 256, 256);

    // 5) transpose back + batch2channel + concat -> out [8,12,256,256]
    gather_kernel<<<dim3(8, 8, 96), dim3(32, 8)>>>(pLL, pHL, pLH, pHH, out);
}

// round 5
// speedup vs baseline: 2.0458x; 1.1050x over previous
#include <cuda_runtime.h>
#include <cstddef>

// ---------------------------------------------------------------------------
// learn_wavelet: 3-level learnable lifting wavelet.
// Subnets: packed f32x2 FMA; hidden tensor in SMEM as fp32 channel-pairs,
// 4 pairs per position (32B), XOR-swizzled. Stage 2 computes 2x4 px/thread
// (tile 32w x 64h, 256 thr, 93.4KB dynamic SMEM, 2 blocks/SM) so vertical tap
// reuse cuts hidden loads 18 -> 12 LDS.128 per pixel. sIn stored duplicated
// (float2) so stage-1 FFMA2 operands come straight from LDS.64.
// ---------------------------------------------------------------------------

#define NIMG 24
typedef unsigned long long ull;

// Scratch (device globals: allocation-free per harness rules)
__device__ float g_L [NIMG * 256 * 512];
__device__ float g_H [NIMG * 256 * 512];
__device__ float g_LL[NIMG * 256 * 256];
__device__ float g_HL[NIMG * 256 * 256];
__device__ float g_LH[NIMG * 256 * 256];
__device__ float g_HH[NIMG * 256 * 256];

// Channel-paired weights: pair p holds (ch 2p, ch 2p+1) in (lo, hi).
struct PackedW {
    ull   w1[2][8][9];   // [pset][pair][tap]
    ull   b1[2][8];
    ull   w2[2][8][9];
    float b2[2];
    float pad[2];
};
__device__   PackedW g_pack;
__constant__ PackedW c_pack;

// ---------------- packed f32x2 helpers ----------------
__device__ __forceinline__ ull fma2(ull a, ull b, ull c) {
    ull d; asm("fma.rn.f32x2 %0, %1, %2, %3;" : "=l"(d) : "l"(a), "l"(b), "l"(c));
    return d;
}
__device__ __forceinline__ ull pack2(float lo, float hi) {
    ull d;
    asm("mov.b64 %0, {%1, %2};" : "=l"(d)
        : "r"(__float_as_uint(lo)), "r"(__float_as_uint(hi)));
    return d;
}
__device__ __forceinline__ float2 unpack2(ull a) {
    unsigned lo, hi;
    asm("mov.b64 {%0, %1}, %2;" : "=r"(lo), "=r"(hi) : "l"(a));
    return make_float2(__uint_as_float(lo), __uint_as_float(hi));
}

// XOR swizzle: bits[7:9] -> bits[4:6]; keeps 128B-strided phases conflict-free.
__device__ __forceinline__ unsigned swz(unsigned b) {
    return b ^ ((b >> 3) & 0x70);
}

// SMEM partition (dynamic): sH (76032B) then sIn (68*36 float2 = 19584B)
#define SH_BYTES   (66 * 36 * 32)
#define SMEM_TOTAL (SH_BYTES + 68 * 36 * 8)

// ---------------------------------------------------------------------------
// Prep kernel: pack channel-paired weights into g_pack (then memcpy to const).
// ---------------------------------------------------------------------------
__global__ void prep_kernel(const float* __restrict__ Wp1, const float* __restrict__ bp1,
                            const float* __restrict__ Wp2, const float* __restrict__ bp2,
                            const float* __restrict__ Wu1, const float* __restrict__ bu1,
                            const float* __restrict__ Wu2, const float* __restrict__ bu2)
{
    int t = threadIdx.x;
    const float* W1s[2] = {Wp1, Wu1};
    const float* B1s[2] = {bp1, bu1};
    const float* W2s[2] = {Wp2, Wu2};
    const float* B2s[2] = {bp2, bu2};
    if (t < 144) {
        int ps = t / 72, r = t - ps * 72, p = r / 9, k = r - p * 9;
        *(float2*)&g_pack.w1[ps][p][k] =
            make_float2(W1s[ps][(2 * p) * 9 + k], W1s[ps][(2 * p + 1) * 9 + k]);
        *(float2*)&g_pack.w2[ps][p][k] =
            make_float2(W2s[ps][(2 * p) * 9 + k], W2s[ps][(2 * p + 1) * 9 + k]);
    }
    if (t < 16) {
        int ps = t / 8, p = t - ps * 8;
        *(float2*)&g_pack.b1[ps][p] = make_float2(B1s[ps][2 * p], B1s[ps][2 * p + 1]);
    }
    if (t < 2) g_pack.b2[t] = B2s[t][0];
}

// ---------------------------------------------------------------------------
// Kernel 1: RGB->YUV + even/odd row split.
// ---------------------------------------------------------------------------
__global__ void yuv_split_kernel(const float* __restrict__ x,
                                 float* __restrict__ L, float* __restrict__ H)
{
    int b   = blockIdx.y;
    int idx = blockIdx.x * 256 + threadIdx.x;
    int y   = idx >> 9;
    int xx  = idx & 511;

    const float* xb = x + (size_t)b * 3 * 262144;
    float r  = xb[idx];
    float g  = xb[262144 + idx];
    float bl = xb[2 * 262144 + idx];

    float Y =  0.299f * r + 0.587f * g + 0.114f * bl;
    float U = -0.147f * r - 0.289f * g + 0.436f * bl;
    float V =  0.615f * r - 0.515f * g - 0.100f * bl;

    float* dst = (y & 1) ? H : L;
    size_t o = (size_t)(y >> 1) * 512 + xx;
    const size_t istr = (size_t)256 * 512;
    dst[(size_t)(0 * 8 + b) * istr + o] = Y;
    dst[(size_t)(1 * 8 + b) * istr + o] = U;
    dst[(size_t)(2 * 8 + b) * istr + o] = V;
}

// ---------------------------------------------------------------------------
// Kernel 2: fused subnet + lift.  O[p] = S[p] + sign*subnet(I)[p]
// Tile 32w x 64h, 256 threads, 2 passes of 8 channels (4 pairs).
// Hidden: per position (hy<66, hx<34, pitch 36) 4 fp32 pairs = 32B, swizzled.
// Stage 2: 8 px/thread (rows 2r,2r+1 x 4 cols) -> 12 LDS.128/px.
// SAME padding of conv2 zero-pads the *hidden* tensor (off-image hidden = 0).
// ---------------------------------------------------------------------------
__global__ void __launch_bounds__(256, 2)
subnet_lift_kernel(const float* __restrict__ I, const float* __restrict__ S,
                   float* __restrict__ O, int pset, float sign, int h, int w)
{
    extern __shared__ char dynsmem[];
    char*   sHb = dynsmem;                          // 66*36 pos * 32B
    float2* sIn = (float2*)(dynsmem + SH_BYTES);    // 68 rows * 36 cols, duplicated

    const int tid = threadIdx.x;
    const int img = blockIdx.z;
    const int bx = blockIdx.x * 32;
    const int by = blockIdx.y * 64;
    const float* Ii = I + (size_t)img * h * w;

    // --- load input tile (rows by-2..by+65, cols bx-2..bx+33), duplicated ---
    for (int idx = tid; idx < 68 * 36; idx += 256) {
        int ly = idx / 36, lx = idx - ly * 36;
        int gy = by + ly - 2, gx = bx + lx - 2;
        float v = 0.f;
        if (gy >= 0 && gy < h && gx >= 0 && gx < w)
            v = Ii[(size_t)gy * w + gx];
        sIn[idx] = make_float2(v, v);
    }
    __syncthreads();

    // stage-2 ownership: rows 2r, 2r+1; cols oxq..oxq+3
    const int r   = tid >> 3;            // 0..31
    const int oxq = (tid & 7) * 4;       // 0,4,...,28

    const ull bias2 = pack2(c_pack.b2[pset], 0.f);  // bias once per px (lo)
    ull a00 = bias2, a01 = bias2, a02 = bias2, a03 = bias2;  // row 2r
    ull a10 = bias2, a11 = bias2, a12 = bias2, a13 = bias2;  // row 2r+1

    for (int g = 0; g < 2; g++) {
        // --- stage 1: conv 1->8 (pairs 4g..4g+3) + relu -> packed SMEM ---
        for (int idx = tid; idx < 66 * 34; idx += 256) {
            int hy = idx / 34, hx = idx - hy * 34;

            ull c0 = c_pack.b1[pset][4 * g + 0];
            ull c1 = c_pack.b1[pset][4 * g + 1];
            ull c2 = c_pack.b1[pset][4 * g + 2];
            ull c3 = c_pack.b1[pset][4 * g + 3];
#pragma unroll
            for (int k = 0; k < 9; k++) {
                int dy = k / 3, dx = k - dy * 3;
                ull vp = *(const ull*)&sIn[(hy + dy) * 36 + hx + dx];
                c0 = fma2(c_pack.w1[pset][4 * g + 0][k], vp, c0);
                c1 = fma2(c_pack.w1[pset][4 * g + 1][k], vp, c1);
                c2 = fma2(c_pack.w1[pset][4 * g + 2][k], vp, c2);
                c3 = fma2(c_pack.w1[pset][4 * g + 3][k], vp, c3);
            }

            int gy = by + hy - 1, gx = bx + hx - 1;
            bool valid = (gy >= 0 && gy < h && gx >= 0 && gx < w);
            float2 f0 = unpack2(c0), f1 = unpack2(c1),
                   f2 = unpack2(c2), f3 = unpack2(c3);
            float4 v0, v1;
            v0.x = valid ? fmaxf(f0.x, 0.f) : 0.f;
            v0.y = valid ? fmaxf(f0.y, 0.f) : 0.f;
            v0.z = valid ? fmaxf(f1.x, 0.f) : 0.f;
            v0.w = valid ? fmaxf(f1.y, 0.f) : 0.f;
            v1.x = valid ? fmaxf(f2.x, 0.f) : 0.f;
            v1.y = valid ? fmaxf(f2.y, 0.f) : 0.f;
            v1.z = valid ? fmaxf(f3.x, 0.f) : 0.f;
            v1.w = valid ? fmaxf(f3.y, 0.f) : 0.f;

            unsigned b0 = (unsigned)(hy * 36 + hx) * 32;
            *(float4*)(sHb + swz(b0))      = v0;   // pairs 4g, 4g+1
            *(float4*)(sHb + swz(b0 + 16)) = v1;   // pairs 4g+2, 4g+3
        }
        __syncthreads();

        // --- stage 2 partial: conv 8->1, 2 output rows sharing hidden rows ---
#pragma unroll
        for (int hr = 0; hr < 4; hr++) {
            const int hy = 2 * r + hr;
#pragma unroll
            for (int ck = 0; ck < 2; ck++) {
                const ull* wA = c_pack.w2[pset][4 * g + 2 * ck];
                const ull* wB = c_pack.w2[pset][4 * g + 2 * ck + 1];
                unsigned base = (unsigned)(hy * 36 + oxq) * 32 + ck * 16;
                ull A[6], B[6];
#pragma unroll
                for (int j = 0; j < 6; j++) {
                    ulonglong2 v =
                        *(const ulonglong2*)(sHb + swz(base + j * 32));
                    A[j] = v.x; B[j] = v.y;
                }
                if (hr <= 2) {            // contributes to output row 2r (dy=hr)
#pragma unroll
                    for (int t = 0; t < 3; t++) {
                        ull wa = wA[hr * 3 + t], wb = wB[hr * 3 + t];
                        a00 = fma2(wa, A[t],     a00);
                        a01 = fma2(wa, A[t + 1], a01);
                        a02 = fma2(wa, A[t + 2], a02);
                        a03 = fma2(wa, A[t + 3], a03);
                        a00 = fma2(wb, B[t],     a00);
                        a01 = fma2(wb, B[t + 1], a01);
                        a02 = fma2(wb, B[t + 2], a02);
                        a03 = fma2(wb, B[t + 3], a03);
                    }
                }
                if (hr >= 1) {            // contributes to row 2r+1 (dy=hr-1)
#pragma unroll
                    for (int t = 0; t < 3; t++) {
                        ull wa = wA[(hr - 1) * 3 + t], wb = wB[(hr - 1) * 3 + t];
                        a10 = fma2(wa, A[t],     a10);
                        a11 = fma2(wa, A[t + 1], a11);
                        a12 = fma2(wa, A[t + 2], a12);
                        a13 = fma2(wa, A[t + 3], a13);
                        a10 = fma2(wb, B[t],     a10);
                        a11 = fma2(wb, B[t + 1], a11);
                        a12 = fma2(wb, B[t + 2], a12);
                        a13 = fma2(wb, B[t + 3], a13);
                    }
                }
            }
        }
        if (g == 0) __syncthreads();   // before next pass overwrites sH
    }

    // --- epilogue: O = S + sign*acc, float4 per row ---
    float2 f00 = unpack2(a00), f01 = unpack2(a01),
           f02 = unpack2(a02), f03 = unpack2(a03);
    float2 f10 = unpack2(a10), f11 = unpack2(a11),
           f12 = unpack2(a12), f13 = unpack2(a13);

    const float* Si = S + (size_t)img * h * w;
    float* Oi = O + (size_t)img * h * w;
    size_t p0 = (size_t)(by + 2 * r) * w + bx + oxq;
    size_t p1 = p0 + w;

    float4 s0 = *(const float4*)(Si + p0);
    float4 s1 = *(const float4*)(Si + p1);
    float4 o0, o1;
    o0.x = s0.x + sign * (f00.x + f00.y);
    o0.y = s0.y + sign * (f01.x + f01.y);
    o0.z = s0.z + sign * (f02.x + f02.y);
    o0.w = s0.w + sign * (f03.x + f03.y);
    o1.x = s1.x + sign * (f10.x + f10.y);
    o1.y = s1.y + sign * (f11.x + f11.y);
    o1.z = s1.z + sign * (f12.x + f12.y);
    o1.w = s1.w + sign * (f13.x + f13.y);
    *(float4*)(Oi + p0) = o0;
    *(float4*)(Oi + p1) = o1;
}

// ---------------------------------------------------------------------------
// Kernel 3: transpose + even/odd split (L and H via grid.z).
// ---------------------------------------------------------------------------
__global__ void transpose_split_kernel(const float* __restrict__ Lsrc,
                                       const float* __restrict__ Hsrc,
                                       float* __restrict__ LLd, float* __restrict__ HLd,
                                       float* __restrict__ LHd, float* __restrict__ HHd,
                                       int h, int w)
{
    __shared__ float tile[32][65];
    int z = blockIdx.z;
    int which = z / NIMG, img = z - which * NIMG;
    const float* T = which ? Hsrc : Lsrc;
    float* E = which ? LHd : LLd;
    float* O = which ? HHd : HLd;

    const int c0 = blockIdx.x * 32;
    const int r0 = blockIdx.y * 32;
    const int tx = threadIdx.x, ty = threadIdx.y;

    const float* Ti = T + (size_t)img * h * w;
#pragma unroll
    for (int k = 0; k < 4; k++) {
        int cc = ty + 8 * k;
        const float* row = Ti + (size_t)(c0 + cc) * w + 2 * r0;
        tile[cc][tx]      = row[tx];
        tile[cc][tx + 32] = row[tx + 32];
    }
    __syncthreads();

    size_t imgo = (size_t)img * (w / 2) * h;
#pragma unroll
    for (int k = 0; k < 4; k++) {
        int rr = ty + 8 * k;
        size_t o = imgo + (size_t)(r0 + rr) * h + c0 + tx;
        E[o] = tile[tx][2 * rr];
        O[o] = tile[tx][2 * rr + 1];
    }
}

// ---------------------------------------------------------------------------
// Kernel 4: gather. out[b, q*3+c, i, j] = Q_q[c*8+b, j, i]
// ---------------------------------------------------------------------------
__global__ void gather_kernel(const float* __restrict__ LL, const float* __restrict__ HL,
                              const float* __restrict__ LH, const float* __restrict__ HH,
                              float* __restrict__ out)
{
    __shared__ float tile[32][33];
    int z = blockIdx.z;
    int q = z / NIMG, img = z - q * NIMG;
    const float* Q = (q == 0) ? LL : (q == 1) ? HL : (q == 2) ? LH : HH;
    int b = img & 7, cch = img >> 3;
    int chan = q * 3 + cch;

    int i0 = blockIdx.x * 32, j0 = blockIdx.y * 32;
    int tx = threadIdx.x, ty = threadIdx.y;

    const float* Qi = Q + (size_t)img * 65536;
#pragma unroll
    for (int k = 0; k < 4; k++) {
        int jj = ty + 8 * k;
        tile[jj][tx] = Qi[(size_t)(j0 + jj) * 256 + i0 + tx];
    }
    __syncthreads();

    float* o = out + ((size_t)b * 12 + chan) * 65536;
#pragma unroll
    for (int k = 0; k < 4; k++) {
        int ii = ty + 8 * k;
        o[(size_t)(i0 + ii) * 256 + j0 + tx] = tile[tx][ii];
    }
}

// ---------------------------------------------------------------------------
extern "C" void kernel_launch(void* const* d_in, const int* in_sizes, int n_in,
                              void* d_out, int out_size)
{
    const float* x   = (const float*)d_in[0];
    const float* Wp1 = (const float*)d_in[1];
    const float* bp1 = (const float*)d_in[2];
    const float* Wp2 = (const float*)d_in[3];
    const float* bp2 = (const float*)d_in[4];
    const float* Wu1 = (const float*)d_in[5];
    const float* bu1 = (const float*)d_in[6];
    const float* Wu2 = (const float*)d_in[7];
    const float* bu2 = (const float*)d_in[8];
    float* out = (float*)d_out;

    // opt in to >48KB dynamic SMEM (idempotent)
    cudaFuncSetAttribute(subnet_lift_kernel,
                         cudaFuncAttributeMaxDynamicSharedMemorySize, SMEM_TOTAL);

    // pack weights on device, then stage into __constant__
    prep_kernel<<<1, 256>>>(Wp1, bp1, Wp2, bp2, Wu1, bu1, Wu2, bu2);
    PackedW* pg;
    cudaGetSymbolAddress((void**)&pg, g_pack);
    cudaMemcpyToSymbolAsync(c_pack, pg, sizeof(PackedW), 0, cudaMemcpyDeviceToDevice);

    float *pL, *pH, *pLL, *pHL, *pLH, *pHH;
    cudaGetSymbolAddress((void**)&pL,  g_L);
    cudaGetSymbolAddress((void**)&pH,  g_H);
    cudaGetSymbolAddress((void**)&pLL, g_LL);
    cudaGetSymbolAddress((void**)&pHL, g_HL);
    cudaGetSymbolAddress((void**)&pLH, g_LH);
    cudaGetSymbolAddress((void**)&pHH, g_HH);

    // 1) rgb->yuv + row split
    yuv_split_kernel<<<dim3(1024, 8), 256>>>(x, pL, pH);

    // 2) lift 1 (rows), 24 x 256 x 512 ; tiles 32w x 64h
    dim3 g1(512 / 32, 256 / 64, NIMG);
    subnet_lift_kernel<<<g1, 256, SMEM_TOTAL>>>(pL, pH, pH, 0, -1.f, 256, 512);
    subnet_lift_kernel<<<g1, 256, SMEM_TOTAL>>>(pH, pL, pL, 1, +1.f, 256, 512);

    // 3) transpose + column split
    dim3 gt(256 / 32, 256 / 32, 2 * NIMG);
    transpose_split_kernel<<<gt, dim3(32, 8)>>>(pL, pH, pLL, pHL, pLH, pHH, 256, 512);

    // 4) lift 2 (L branch) and lift 3 (H branch), each 24 x 256 x 256
    dim3 g2(256 / 32, 256 / 64, NIMG);
    subnet_lift_kernel<<<g2, 256, SMEM_TOTAL>>>(pLL, pHL, pHL, 0, -1.f, 256, 256);
    subnet_lift_kernel<<<g2, 256, SMEM_TOTAL>>>(pHL, pLL, pLL, 1, +1.f, 256, 256);
    subnet_lift_kernel<<<g2, 256, SMEM_TOTAL>>>(pLH, pHH, pHH, 0, -1.f, 256, 256);
    subnet_lift_kernel<<<g2, 256, SMEM_TOTAL>>>(pHH, pLH, pLH, 1, +1.f, 256, 256);

    // 5) transpose back + batch2channel + concat -> out [8,12,256,256]
    gather_kernel<<<dim3(8, 8, 96), dim3(32, 8)>>>(pLL, pHL, pLH, pHH, out);
}

// round 8
// speedup vs baseline: 2.4687x; 1.2067x over previous
#include <cuda_runtime.h>
#include <cstddef>

// ---------------------------------------------------------------------------
// learn_wavelet: 3-level learnable lifting wavelet.
// Subnets: packed f32x2 FMA; hidden tensor in SMEM as fp32 channel-pairs,
// 4 pairs / position (32B), XOR-swizzled. 2x4 px/thread. Register budget
// capped at ~112 via __launch_bounds__(288,2) so 2 blocks/SM stay resident.
// NOTE on swizzle reuse: swz(x+16) == swz(x) ^ 16 (NOT +16) for x % 32 == 0.
// ---------------------------------------------------------------------------

#define NIMG 24
typedef unsigned long long ull;

// Scratch (device globals: allocation-free per harness rules)
__device__ float g_L [NIMG * 256 * 512];
__device__ float g_H [NIMG * 256 * 512];
__device__ float g_LL[NIMG * 256 * 256];
__device__ float g_HL[NIMG * 256 * 256];
__device__ float g_LH[NIMG * 256 * 256];
__device__ float g_HH[NIMG * 256 * 256];

// Channel-paired weights: pair p holds (ch 2p, ch 2p+1) in (lo, hi).
struct PackedW {
    ull   w1[2][8][9];   // [pset][pair][tap]
    ull   b1[2][8];
    ull   w2[2][8][9];
    float b2[2];
    float pad[2];
};
__device__   PackedW g_pack;
__constant__ PackedW c_pack;

// ---------------- packed f32x2 helpers ----------------
__device__ __forceinline__ ull fma2(ull a, ull b, ull c) {
    ull d; asm("fma.rn.f32x2 %0, %1, %2, %3;" : "=l"(d) : "l"(a), "l"(b), "l"(c));
    return d;
}
__device__ __forceinline__ ull pack2(float lo, float hi) {
    ull d;
    asm("mov.b64 %0, {%1, %2};" : "=l"(d)
        : "r"(__float_as_uint(lo)), "r"(__float_as_uint(hi)));
    return d;
}
__device__ __forceinline__ float2 unpack2(ull a) {
    unsigned lo, hi;
    asm("mov.b64 {%0, %1}, %2;" : "=r"(lo), "=r"(hi) : "l"(a));
    return make_float2(__uint_as_float(lo), __uint_as_float(hi));
}

// XOR swizzle: bits[7:9] -> bits[4:6].
__device__ __forceinline__ unsigned swz(unsigned b) {
    return b ^ ((b >> 3) & 0x70);
}

// SMEM partition (dynamic): sH (76032B) then sIn (68*36 float2 = 19584B)
#define SH_BYTES   (66 * 36 * 32)
#define SMEM_TOTAL (SH_BYTES + 68 * 36 * 8)

// ---------------------------------------------------------------------------
// Prep kernel: pack channel-paired weights into g_pack (then memcpy to const).
// ---------------------------------------------------------------------------
__global__ void prep_kernel(const float* __restrict__ Wp1, const float* __restrict__ bp1,
                            const float* __restrict__ Wp2, const float* __restrict__ bp2,
                            const float* __restrict__ Wu1, const float* __restrict__ bu1,
                            const float* __restrict__ Wu2, const float* __restrict__ bu2)
{
    int t = threadIdx.x;
    const float* W1s[2] = {Wp1, Wu1};
    const float* B1s[2] = {bp1, bu1};
    const float* W2s[2] = {Wp2, Wu2};
    const float* B2s[2] = {bp2, bu2};
    if (t < 144) {
        int ps = t / 72, r = t - ps * 72, p = r / 9, k = r - p * 9;
        *(float2*)&g_pack.w1[ps][p][k] =
            make_float2(W1s[ps][(2 * p) * 9 + k], W1s[ps][(2 * p + 1) * 9 + k]);
        *(float2*)&g_pack.w2[ps][p][k] =
            make_float2(W2s[ps][(2 * p) * 9 + k], W2s[ps][(2 * p + 1) * 9 + k]);
    }
    if (t < 16) {
        int ps = t / 8, p = t - ps * 8;
        *(float2*)&g_pack.b1[ps][p] = make_float2(B1s[ps][2 * p], B1s[ps][2 * p + 1]);
    }
    if (t < 2) g_pack.b2[t] = B2s[t][0];
}

// ---------------------------------------------------------------------------
// Kernel 1: RGB->YUV + even/odd row split.
// ---------------------------------------------------------------------------
__global__ void yuv_split_kernel(const float* __restrict__ x,
                                 float* __restrict__ L, float* __restrict__ H)
{
    int b   = blockIdx.y;
    int idx = blockIdx.x * 256 + threadIdx.x;
    int y   = idx >> 9;
    int xx  = idx & 511;

    const float* xb = x + (size_t)b * 3 * 262144;
    float r  = xb[idx];
    float g  = xb[262144 + idx];
    float bl = xb[2 * 262144 + idx];

    float Y =  0.299f * r + 0.587f * g + 0.114f * bl;
    float U = -0.147f * r - 0.289f * g + 0.436f * bl;
    float V =  0.615f * r - 0.515f * g - 0.100f * bl;

    float* dst = (y & 1) ? H : L;
    size_t o = (size_t)(y >> 1) * 512 + xx;
    const size_t istr = (size_t)256 * 512;
    dst[(size_t)(0 * 8 + b) * istr + o] = Y;
    dst[(size_t)(1 * 8 + b) * istr + o] = U;
    dst[(size_t)(2 * 8 + b) * istr + o] = V;
}

// ---------------------------------------------------------------------------
// Stage-1 helper: conv 1->8 (pairs 4g..4g+3) + relu -> packed swizzled SMEM.
// CHK=false for interior blocks (no SAME-pad exposure): skips validity mask.
// ---------------------------------------------------------------------------
template <bool CHK>
__device__ __forceinline__ void stage1(const float2* sIn, char* sHb,
                                       int pset, int g, int by, int bx,
                                       int h, int w, int tid)
{
    for (int idx = tid; idx < 66 * 34; idx += 256) {
        int hy = idx / 34, hx = idx - hy * 34;

        ull c0 = c_pack.b1[pset][4 * g + 0];
        ull c1 = c_pack.b1[pset][4 * g + 1];
        ull c2 = c_pack.b1[pset][4 * g + 2];
        ull c3 = c_pack.b1[pset][4 * g + 3];
#pragma unroll
        for (int k = 0; k < 9; k++) {
            int dy = k / 3, dx = k - dy * 3;
            ull vp = *(const ull*)&sIn[(hy + dy) * 36 + hx + dx];
            c0 = fma2(c_pack.w1[pset][4 * g + 0][k], vp, c0);
            c1 = fma2(c_pack.w1[pset][4 * g + 1][k], vp, c1);
            c2 = fma2(c_pack.w1[pset][4 * g + 2][k], vp, c2);
            c3 = fma2(c_pack.w1[pset][4 * g + 3][k], vp, c3);
        }

        bool valid = true;
        if (CHK) {
            int gy = by + hy - 1, gx = bx + hx - 1;
            valid = (gy >= 0 && gy < h && gx >= 0 && gx < w);
        }
        float2 f0 = unpack2(c0), f1 = unpack2(c1),
               f2 = unpack2(c2), f3 = unpack2(c3);
        float4 v0, v1;
        v0.x = valid ? fmaxf(f0.x, 0.f) : 0.f;
        v0.y = valid ? fmaxf(f0.y, 0.f) : 0.f;
        v0.z = valid ? fmaxf(f1.x, 0.f) : 0.f;
        v0.w = valid ? fmaxf(f1.y, 0.f) : 0.f;
        v1.x = valid ? fmaxf(f2.x, 0.f) : 0.f;
        v1.y = valid ? fmaxf(f2.y, 0.f) : 0.f;
        v1.z = valid ? fmaxf(f3.x, 0.f) : 0.f;
        v1.w = valid ? fmaxf(f3.y, 0.f) : 0.f;

        unsigned b0 = (unsigned)(hy * 36 + hx) * 32;
        unsigned a0 = swz(b0);
        *(float4*)(sHb + a0)        = v0;   // pairs 4g, 4g+1
        *(float4*)(sHb + (a0 ^ 16)) = v1;   // pairs 4g+2, 4g+3 (swz(b0+16)=swz(b0)^16)
    }
}

// ---------------------------------------------------------------------------
// Kernel 2: fused subnet + lift.  O[p] = S[p] + sign*subnet(I)[p]
// Tile 32w x 64h, 256 threads, 2 passes of 8 channels (4 pairs).
// grid.z in [0, 2*NIMG): z < NIMG uses buffer set A, else set B (lets lift2
// and lift3 share one launch). __launch_bounds__(288,2) caps regs ~112 so
// 2 blocks/SM actually fit the register file.
// SAME padding of conv2 zero-pads the *hidden* tensor (off-image hidden = 0).
// ---------------------------------------------------------------------------
__global__ void __launch_bounds__(288, 2)
subnet_lift_kernel(const float* __restrict__ IA, const float* __restrict__ SA,
                   float* __restrict__ OA,
                   const float* __restrict__ IB, const float* __restrict__ SB,
                   float* __restrict__ OB,
                   int pset, float sign, int h, int w)
{
    extern __shared__ char dynsmem[];
    char*   sHb = dynsmem;                          // 66*36 pos * 32B
    float2* sIn = (float2*)(dynsmem + SH_BYTES);    // 68 rows * 36 cols, dup'd

    const int tid = threadIdx.x;
    int z = blockIdx.z;
    const int setB = (z >= NIMG);
    const int img  = setB ? z - NIMG : z;
    const float* I = setB ? IB : IA;
    const float* S = setB ? SB : SA;
    float*       O = setB ? OB : OA;

    const int bx = blockIdx.x * 32;
    const int by = blockIdx.y * 64;
    const float* Ii = I + (size_t)img * h * w;

    const bool interior = (bx >= 2) && (bx + 34 <= w) &&
                          (by >= 2) && (by + 66 <= h);

    // --- load input tile (rows by-2..by+65, cols bx-2..bx+33), duplicated ---
    if (interior) {
        for (int idx = tid; idx < 68 * 36; idx += 256) {
            int ly = idx / 36, lx = idx - ly * 36;
            float v = Ii[(size_t)(by + ly - 2) * w + (bx + lx - 2)];
            sIn[idx] = make_float2(v, v);
        }
    } else {
        for (int idx = tid; idx < 68 * 36; idx += 256) {
            int ly = idx / 36, lx = idx - ly * 36;
            int gy = by + ly - 2, gx = bx + lx - 2;
            float v = 0.f;
            if (gy >= 0 && gy < h && gx >= 0 && gx < w)
                v = Ii[(size_t)gy * w + gx];
            sIn[idx] = make_float2(v, v);
        }
    }
    __syncthreads();

    // stage-2 ownership: rows 2r, 2r+1; cols oxq..oxq+3
    const int r   = tid >> 3;            // 0..31
    const int oxq = (tid & 7) * 4;       // 0,4,...,28

    const ull bias2 = pack2(c_pack.b2[pset], 0.f);  // bias once per px (lo)
    ull a00 = bias2, a01 = bias2, a02 = bias2, a03 = bias2;  // row 2r
    ull a10 = bias2, a11 = bias2, a12 = bias2, a13 = bias2;  // row 2r+1

#pragma unroll 1
    for (int g = 0; g < 2; g++) {
        if (interior)
            stage1<false>(sIn, sHb, pset, g, by, bx, h, w, tid);
        else
            stage1<true>(sIn, sHb, pset, g, by, bx, h, w, tid);
        __syncthreads();

        // --- stage 2 partial: conv 8->1, 2 output rows sharing hidden rows ---
#pragma unroll
        for (int hr = 0; hr < 4; hr++) {
            const int hy = 2 * r + hr;
            unsigned base = (unsigned)(hy * 36 + oxq) * 32;
            unsigned ad[6];
#pragma unroll
            for (int j = 0; j < 6; j++) ad[j] = swz(base + j * 32);

#pragma unroll
            for (int ck = 0; ck < 2; ck++) {
                const ull* wA = c_pack.w2[pset][4 * g + 2 * ck];
                const ull* wB = wA + 9;     // next pair, contiguous
                ull A[6], B[6];
#pragma unroll
                for (int j = 0; j < 6; j++) {
                    // swz(x+16) == swz(x) ^ 16 for x % 32 == 0  (XOR, not +)
                    ulonglong2 v =
                        *(const ulonglong2*)(sHb + (ad[j] ^ (ck * 16)));
                    A[j] = v.x; B[j] = v.y;
                }
                if (hr <= 2) {            // contributes to row 2r (dy = hr)
#pragma unroll
                    for (int t = 0; t < 3; t++) {
                        ull wa = wA[hr * 3 + t], wb = wB[hr * 3 + t];
                        a00 = fma2(wa, A[t],     a00);
                        a01 = fma2(wa, A[t + 1], a01);
                        a02 = fma2(wa, A[t + 2], a02);
                        a03 = fma2(wa, A[t + 3], a03);
                        a00 = fma2(wb, B[t],     a00);
                        a01 = fma2(wb, B[t + 1], a01);
                        a02 = fma2(wb, B[t + 2], a02);
                        a03 = fma2(wb, B[t + 3], a03);
                    }
                }
                if (hr >= 1) {            // contributes to row 2r+1 (dy = hr-1)
#pragma unroll
                    for (int t = 0; t < 3; t++) {
                        ull wa = wA[(hr - 1) * 3 + t], wb = wB[(hr - 1) * 3 + t];
                        a10 = fma2(wa, A[t],     a10);
                        a11 = fma2(wa, A[t + 1], a11);
                        a12 = fma2(wa, A[t + 2], a12);
                        a13 = fma2(wa, A[t + 3], a13);
                        a10 = fma2(wb, B[t],     a10);
                        a11 = fma2(wb, B[t + 1], a11);
                        a12 = fma2(wb, B[t + 2], a12);
                        a13 = fma2(wb, B[t + 3], a13);
                    }
                }
            }
        }
        if (g == 0) __syncthreads();   // before next pass overwrites sH
    }

    // --- epilogue: O = S + sign*acc, float4 per row ---
    float2 f00 = unpack2(a00), f01 = unpack2(a01),
           f02 = unpack2(a02), f03 = unpack2(a03);
    float2 f10 = unpack2(a10), f11 = unpack2(a11),
           f12 = unpack2(a12), f13 = unpack2(a13);

    const float* Si = S + (size_t)img * h * w;
    float* Oi = O + (size_t)img * h * w;
    size_t p0 = (size_t)(by + 2 * r) * w + bx + oxq;
    size_t p1 = p0 + w;

    float4 s0 = *(const float4*)(Si + p0);
    float4 s1 = *(const float4*)(Si + p1);
    float4 o0, o1;
    o0.x = s0.x + sign * (f00.x + f00.y);
    o0.y = s0.y + sign * (f01.x + f01.y);
    o0.z = s0.z + sign * (f02.x + f02.y);
    o0.w = s0.w + sign * (f03.x + f03.y);
    o1.x = s1.x + sign * (f10.x + f10.y);
    o1.y = s1.y + sign * (f11.x + f11.y);
    o1.z = s1.z + sign * (f12.x + f12.y);
    o1.w = s1.w + sign * (f13.x + f13.y);
    *(float4*)(Oi + p0) = o0;
    *(float4*)(Oi + p1) = o1;
}

// ---------------------------------------------------------------------------
// Kernel 3: transpose + even/odd split (L and H via grid.z).
// ---------------------------------------------------------------------------
__global__ void transpose_split_kernel(const float* __restrict__ Lsrc,
                                       const float* __restrict__ Hsrc,
                                       float* __restrict__ LLd, float* __restrict__ HLd,
                                       float* __restrict__ LHd, float* __restrict__ HHd,
                                       int h, int w)
{
    __shared__ float tile[32][65];
    int z = blockIdx.z;
    int which = z / NIMG, img = z - which * NIMG;
    const float* T = which ? Hsrc : Lsrc;
    float* E = which ? LHd : LLd;
    float* O = which ? HHd : HLd;

    const int c0 = blockIdx.x * 32;
    const int r0 = blockIdx.y * 32;
    const int tx = threadIdx.x, ty = threadIdx.y;

    const float* Ti = T + (size_t)img * h * w;
#pragma unroll
    for (int k = 0; k < 4; k++) {
        int cc = ty + 8 * k;
        const float* row = Ti + (size_t)(c0 + cc) * w + 2 * r0;
        tile[cc][tx]      = row[tx];
        tile[cc][tx + 32] = row[tx + 32];
    }
    __syncthreads();

    size_t imgo = (size_t)img * (w / 2) * h;
#pragma unroll
    for (int k = 0; k < 4; k++) {
        int rr = ty + 8 * k;
        size_t o = imgo + (size_t)(r0 + rr) * h + c0 + tx;
        E[o] = tile[tx][2 * rr];
        O[o] = tile[tx][2 * rr + 1];
    }
}

// ---------------------------------------------------------------------------
// Kernel 4: gather. out[b, q*3+c, i, j] = Q_q[c*8+b, j, i]
// ---------------------------------------------------------------------------
__global__ void gather_kernel(const float* __restrict__ LL, const float* __restrict__ HL,
                              const float* __restrict__ LH, const float* __restrict__ HH,
                              float* __restrict__ out)
{
    __shared__ float tile[32][33];
    int z = blockIdx.z;
    int q = z / NIMG, img = z - q * NIMG;
    const float* Q = (q == 0) ? LL : (q == 1) ? HL : (q == 2) ? LH : HH;
    int b = img & 7, cch = img >> 3;
    int chan = q * 3 + cch;

    int i0 = blockIdx.x * 32, j0 = blockIdx.y * 32;
    int tx = threadIdx.x, ty = threadIdx.y;

    const float* Qi = Q + (size_t)img * 65536;
#pragma unroll
    for (int k = 0; k < 4; k++) {
        int jj = ty + 8 * k;
        tile[jj][tx] = Qi[(size_t)(j0 + jj) * 256 + i0 + tx];
    }
    __syncthreads();

    float* o = out + ((size_t)b * 12 + chan) * 65536;
#pragma unroll
    for (int k = 0; k < 4; k++) {
        int ii = ty + 8 * k;
        o[(size_t)(i0 + ii) * 256 + j0 + tx] = tile[tx][ii];
    }
}

// ---------------------------------------------------------------------------
extern "C" void kernel_launch(void* const* d_in, const int* in_sizes, int n_in,
                              void* d_out, int out_size)
{
    const float* x   = (const float*)d_in[0];
    const float* Wp1 = (const float*)d_in[1];
    const float* bp1 = (const float*)d_in[2];
    const float* Wp2 = (const float*)d_in[3];
    const float* bp2 = (const float*)d_in[4];
    const float* Wu1 = (const float*)d_in[5];
    const float* bu1 = (const float*)d_in[6];
    const float* Wu2 = (const float*)d_in[7];
    const float* bu2 = (const float*)d_in[8];
    float* out = (float*)d_out;

    // opt in to >48KB dynamic SMEM (idempotent)
    cudaFuncSetAttribute(subnet_lift_kernel,
                         cudaFuncAttributeMaxDynamicSharedMemorySize, SMEM_TOTAL);

    // pack weights on device, then stage into __constant__
    prep_kernel<<<1, 256>>>(Wp1, bp1, Wp2, bp2, Wu1, bu1, Wu2, bu2);
    PackedW* pg;
    cudaGetSymbolAddress((void**)&pg, g_pack);
    cudaMemcpyToSymbolAsync(c_pack, pg, sizeof(PackedW), 0, cudaMemcpyDeviceToDevice);

    float *pL, *pH, *pLL, *pHL, *pLH, *pHH;
    cudaGetSymbolAddress((void**)&pL,  g_L);
    cudaGetSymbolAddress((void**)&pH,  g_H);
    cudaGetSymbolAddress((void**)&pLL, g_LL);
    cudaGetSymbolAddress((void**)&pHL, g_HL);
    cudaGetSymbolAddress((void**)&pLH, g_LH);
    cudaGetSymbolAddress((void**)&pHH, g_HH);

    // 1) rgb->yuv + row split
    yuv_split_kernel<<<dim3(1024, 8), 256>>>(x, pL, pH);

    // 2) lift 1 (rows), 24 x 256 x 512 ; tiles 32w x 64h
    dim3 g1(512 / 32, 256 / 64, NIMG);
    subnet_lift_kernel<<<g1, 256, SMEM_TOTAL>>>(pL, pH, pH, pL, pH, pH,
                                                0, -1.f, 256, 512);
    subnet_lift_kernel<<<g1, 256, SMEM_TOTAL>>>(pH, pL, pL, pH, pL, pL,
                                                1, +1.f, 256, 512);

    // 3) transpose + column split
    dim3 gt(256 / 32, 256 / 32, 2 * NIMG);
    transpose_split_kernel<<<gt, dim3(32, 8)>>>(pL, pH, pLL, pHL, pLH, pHH, 256, 512);

    // 4) lift 2 (L branch) and lift 3 (H branch) fused per step, grid.z = 48
    dim3 g2(256 / 32, 256 / 64, 2 * NIMG);
    subnet_lift_kernel<<<g2, 256, SMEM_TOTAL>>>(pLL, pHL, pHL, pLH, pHH, pHH,
                                                0, -1.f, 256, 256);
    subnet_lift_kernel<<<g2, 256, SMEM_TOTAL>>>(pHL, pLL, pLL, pHH, pLH, pLH,
                                                1, +1.f, 256, 256);

    // 5) transpose back + batch2channel + concat -> out [8,12,256,256]
    gather_kernel<<<dim3(8, 8, 96), dim3(32, 8)>>>(pLL, pHL, pLH, pHH, out);
}

// round 9
// speedup vs baseline: 2.6048x; 1.0551x over previous
#include <cuda_runtime.h>
#include <cstddef>

// ---------------------------------------------------------------------------
// learn_wavelet: 3-level learnable lifting wavelet.
// Subnets: packed f32x2 FMA; hidden tensor in SMEM as fp32 channel-pairs,
// 4 pairs / position (32B), XOR-swizzled. Stage-1 computes 2 adjacent hidden
// positions per thread so shared taps come via LDS.128 (3 loads / 2 pos).
// Stage-2: 2x4 px/thread. __launch_bounds__(288,2) caps regs so 2 blocks/SM.
// NOTE swizzle identity: swz(x+16) == swz(x) ^ 16 for x % 32 == 0.
// ---------------------------------------------------------------------------

#define NIMG 24
typedef unsigned long long ull;

// Scratch (device globals: allocation-free per harness rules)
__device__ float g_L [NIMG * 256 * 512];
__device__ float g_H [NIMG * 256 * 512];
__device__ float g_LL[NIMG * 256 * 256];
__device__ float g_HL[NIMG * 256 * 256];
__device__ float g_LH[NIMG * 256 * 256];
__device__ float g_HH[NIMG * 256 * 256];

// Channel-paired weights: pair p holds (ch 2p, ch 2p+1) in (lo, hi).
struct PackedW {
    ull   w1[2][8][9];   // [pset][pair][tap]
    ull   b1[2][8];
    ull   w2[2][8][9];
    float b2[2];
    float pad[2];
};
__device__   PackedW g_pack;
__constant__ PackedW c_pack;

// ---------------- packed f32x2 helpers ----------------
__device__ __forceinline__ ull fma2(ull a, ull b, ull c) {
    ull d; asm("fma.rn.f32x2 %0, %1, %2, %3;" : "=l"(d) : "l"(a), "l"(b), "l"(c));
    return d;
}
__device__ __forceinline__ ull pack2(float lo, float hi) {
    ull d;
    asm("mov.b64 %0, {%1, %2};" : "=l"(d)
        : "r"(__float_as_uint(lo)), "r"(__float_as_uint(hi)));
    return d;
}
__device__ __forceinline__ float2 unpack2(ull a) {
    unsigned lo, hi;
    asm("mov.b64 {%0, %1}, %2;" : "=r"(lo), "=r"(hi) : "l"(a));
    return make_float2(__uint_as_float(lo), __uint_as_float(hi));
}

// XOR swizzle: bits[7:9] -> bits[4:6].
__device__ __forceinline__ unsigned swz(unsigned b) {
    return b ^ ((b >> 3) & 0x70);
}

// SMEM partition (dynamic): sH (76032B) then sIn (68*36 float2 = 19584B)
#define SH_BYTES   (66 * 36 * 32)
#define SMEM_TOTAL (SH_BYTES + 68 * 36 * 8)

// ---------------------------------------------------------------------------
// Prep kernel: pack channel-paired weights into g_pack (then memcpy to const).
// ---------------------------------------------------------------------------
__global__ void prep_kernel(const float* __restrict__ Wp1, const float* __restrict__ bp1,
                            const float* __restrict__ Wp2, const float* __restrict__ bp2,
                            const float* __restrict__ Wu1, const float* __restrict__ bu1,
                            const float* __restrict__ Wu2, const float* __restrict__ bu2)
{
    int t = threadIdx.x;
    const float* W1s[2] = {Wp1, Wu1};
    const float* B1s[2] = {bp1, bu1};
    const float* W2s[2] = {Wp2, Wu2};
    const float* B2s[2] = {bp2, bu2};
    if (t < 144) {
        int ps = t / 72, r = t - ps * 72, p = r / 9, k = r - p * 9;
        *(float2*)&g_pack.w1[ps][p][k] =
            make_float2(W1s[ps][(2 * p) * 9 + k], W1s[ps][(2 * p + 1) * 9 + k]);
        *(float2*)&g_pack.w2[ps][p][k] =
            make_float2(W2s[ps][(2 * p) * 9 + k], W2s[ps][(2 * p + 1) * 9 + k]);
    }
    if (t < 16) {
        int ps = t / 8, p = t - ps * 8;
        *(float2*)&g_pack.b1[ps][p] = make_float2(B1s[ps][2 * p], B1s[ps][2 * p + 1]);
    }
    if (t < 2) g_pack.b2[t] = B2s[t][0];
}

// ---------------------------------------------------------------------------
// Kernel 1: RGB->YUV + even/odd row split.
// ---------------------------------------------------------------------------
__global__ void yuv_split_kernel(const float* __restrict__ x,
                                 float* __restrict__ L, float* __restrict__ H)
{
    int b   = blockIdx.y;
    int idx = blockIdx.x * 256 + threadIdx.x;
    int y   = idx >> 9;
    int xx  = idx & 511;

    const float* xb = x + (size_t)b * 3 * 262144;
    float r  = xb[idx];
    float g  = xb[262144 + idx];
    float bl = xb[2 * 262144 + idx];

    float Y =  0.299f * r + 0.587f * g + 0.114f * bl;
    float U = -0.147f * r - 0.289f * g + 0.436f * bl;
    float V =  0.615f * r - 0.515f * g - 0.100f * bl;

    float* dst = (y & 1) ? H : L;
    size_t o = (size_t)(y >> 1) * 512 + xx;
    const size_t istr = (size_t)256 * 512;
    dst[(size_t)(0 * 8 + b) * istr + o] = Y;
    dst[(size_t)(1 * 8 + b) * istr + o] = U;
    dst[(size_t)(2 * 8 + b) * istr + o] = V;
}

// ---------------------------------------------------------------------------
// Stage-1 helper: conv 1->8 (pairs 4g..4g+3) + relu for TWO adjacent hidden
// positions per thread. Taps come as LDS.128 of duplicated float2 input
// (taps hx..hx+3 per row = 2 loads). CHK=false for interior blocks.
// ---------------------------------------------------------------------------
template <bool CHK>
__device__ __forceinline__ void stage1(const float2* sIn, char* sHb,
                                       int pset, int g, int by, int bx,
                                       int h, int w, int tid)
{
    // 66 rows x 17 column pairs (hx = 0,2,...,32)
    for (int idx = tid; idx < 66 * 17; idx += 256) {
        int hy = idx / 17, hp = idx - hy * 17;
        int hx = hp * 2;

        ull bA0 = c_pack.b1[pset][4 * g + 0];
        ull bA1 = c_pack.b1[pset][4 * g + 1];
        ull bA2 = c_pack.b1[pset][4 * g + 2];
        ull bA3 = c_pack.b1[pset][4 * g + 3];
        ull cA0 = bA0, cA1 = bA1, cA2 = bA2, cA3 = bA3;  // pos hx
        ull cB0 = bA0, cB1 = bA1, cB2 = bA2, cB3 = bA3;  // pos hx+1

#pragma unroll
        for (int dy = 0; dy < 3; dy++) {
            const ull* row = (const ull*)&sIn[(hy + dy) * 36 + hx];
            ulonglong2 ta = *(const ulonglong2*)row;        // taps hx, hx+1
            ulonglong2 tb = *(const ulonglong2*)(row + 2);  // taps hx+2, hx+3
            ull t0 = ta.x, t1 = ta.y, t2 = tb.x, t3 = tb.y;
#pragma unroll
            for (int p = 0; p < 4; p++) {
                ull w0 = c_pack.w1[pset][4 * g + p][dy * 3 + 0];
                ull w1 = c_pack.w1[pset][4 * g + p][dy * 3 + 1];
                ull w2 = c_pack.w1[pset][4 * g + p][dy * 3 + 2];
                ull ca = (p == 0) ? cA0 : (p == 1) ? cA1 : (p == 2) ? cA2 : cA3;
                ull cb = (p == 0) ? cB0 : (p == 1) ? cB1 : (p == 2) ? cB2 : cB3;
                ca = fma2(w0, t0, ca); cb = fma2(w0, t1, cb);
                ca = fma2(w1, t1, ca); cb = fma2(w1, t2, cb);
                ca = fma2(w2, t2, ca); cb = fma2(w2, t3, cb);
                if (p == 0) { cA0 = ca; cB0 = cb; }
                else if (p == 1) { cA1 = ca; cB1 = cb; }
                else if (p == 2) { cA2 = ca; cB2 = cb; }
                else { cA3 = ca; cB3 = cb; }
            }
        }

        bool validA = true, validB = true;
        if (CHK) {
            int gy = by + hy - 1, gx = bx + hx - 1;
            bool vy = (gy >= 0 && gy < h);
            validA = vy && (gx >= 0 && gx < w);
            validB = vy && (gx + 1 >= 0 && gx + 1 < w);
        }

        // pos hx
        {
            float2 f0 = unpack2(cA0), f1 = unpack2(cA1),
                   f2 = unpack2(cA2), f3 = unpack2(cA3);
            float4 v0, v1;
            v0.x = validA ? fmaxf(f0.x, 0.f) : 0.f;
            v0.y = validA ? fmaxf(f0.y, 0.f) : 0.f;
            v0.z = validA ? fmaxf(f1.x, 0.f) : 0.f;
            v0.w = validA ? fmaxf(f1.y, 0.f) : 0.f;
            v1.x = validA ? fmaxf(f2.x, 0.f) : 0.f;
            v1.y = validA ? fmaxf(f2.y, 0.f) : 0.f;
            v1.z = validA ? fmaxf(f3.x, 0.f) : 0.f;
            v1.w = validA ? fmaxf(f3.y, 0.f) : 0.f;
            unsigned a0 = swz((unsigned)(hy * 36 + hx) * 32);
            *(float4*)(sHb + a0)        = v0;
            *(float4*)(sHb + (a0 ^ 16)) = v1;
        }
        // pos hx+1
        {
            float2 f0 = unpack2(cB0), f1 = unpack2(cB1),
                   f2 = unpack2(cB2), f3 = unpack2(cB3);
            float4 v0, v1;
            v0.x = validB ? fmaxf(f0.x, 0.f) : 0.f;
            v0.y = validB ? fmaxf(f0.y, 0.f) : 0.f;
            v0.z = validB ? fmaxf(f1.x, 0.f) : 0.f;
            v0.w = validB ? fmaxf(f1.y, 0.f) : 0.f;
            v1.x = validB ? fmaxf(f2.x, 0.f) : 0.f;
            v1.y = validB ? fmaxf(f2.y, 0.f) : 0.f;
            v1.z = validB ? fmaxf(f3.x, 0.f) : 0.f;
            v1.w = validB ? fmaxf(f3.y, 0.f) : 0.f;
            unsigned a1 = swz((unsigned)(hy * 36 + hx + 1) * 32);
            *(float4*)(sHb + a1)        = v0;
            *(float4*)(sHb + (a1 ^ 16)) = v1;
        }
    }
}

// ---------------------------------------------------------------------------
// Kernel 2: fused subnet + lift.  O[p] = S[p] + sign*subnet(I)[p]
// Tile 32w x 64h, 256 threads, 2 passes of 8 channels (4 pairs).
// grid.z in [0, 2*NIMG): z < NIMG uses buffer set A, else set B.
// SAME padding of conv2 zero-pads the *hidden* tensor (off-image hidden = 0).
// ---------------------------------------------------------------------------
__global__ void __launch_bounds__(288, 2)
subnet_lift_kernel(const float* __restrict__ IA, const float* __restrict__ SA,
                   float* __restrict__ OA,
                   const float* __restrict__ IB, const float* __restrict__ SB,
                   float* __restrict__ OB,
                   int pset, float sign, int h, int w)
{
    extern __shared__ char dynsmem[];
    char*   sHb = dynsmem;                          // 66*36 pos * 32B
    float2* sIn = (float2*)(dynsmem + SH_BYTES);    // 68 rows * 36 cols, dup'd

    const int tid = threadIdx.x;
    int z = blockIdx.z;
    const int setB = (z >= NIMG);
    const int img  = setB ? z - NIMG : z;
    const float* I = setB ? IB : IA;
    const float* S = setB ? SB : SA;
    float*       O = setB ? OB : OA;

    const int bx = blockIdx.x * 32;
    const int by = blockIdx.y * 64;
    const float* Ii = I + (size_t)img * h * w;

    const bool interior = (bx >= 2) && (bx + 34 <= w) &&
                          (by >= 2) && (by + 66 <= h);

    // --- load input tile (rows by-2..by+65, cols bx-2..bx+33), duplicated ---
    if (interior) {
        for (int idx = tid; idx < 68 * 36; idx += 256) {
            int ly = idx / 36, lx = idx - ly * 36;
            float v = Ii[(size_t)(by + ly - 2) * w + (bx + lx - 2)];
            sIn[idx] = make_float2(v, v);
        }
    } else {
        for (int idx = tid; idx < 68 * 36; idx += 256) {
            int ly = idx / 36, lx = idx - ly * 36;
            int gy = by + ly - 2, gx = bx + lx - 2;
            float v = 0.f;
            if (gy >= 0 && gy < h && gx >= 0 && gx < w)
                v = Ii[(size_t)gy * w + gx];
            sIn[idx] = make_float2(v, v);
        }
    }
    __syncthreads();

    // stage-2 ownership: rows 2r, 2r+1; cols oxq..oxq+3
    const int r   = tid >> 3;            // 0..31
    const int oxq = (tid & 7) * 4;       // 0,4,...,28

    const ull bias2 = pack2(c_pack.b2[pset], 0.f);  // bias once per px (lo)
    ull a00 = bias2, a01 = bias2, a02 = bias2, a03 = bias2;  // row 2r
    ull a10 = bias2, a11 = bias2, a12 = bias2, a13 = bias2;  // row 2r+1

#pragma unroll 1
    for (int g = 0; g < 2; g++) {
        if (interior)
            stage1<false>(sIn, sHb, pset, g, by, bx, h, w, tid);
        else
            stage1<true>(sIn, sHb, pset, g, by, bx, h, w, tid);
        __syncthreads();

        // --- stage 2 partial: conv 8->1, 2 output rows sharing hidden rows ---
#pragma unroll
        for (int hr = 0; hr < 4; hr++) {
            const int hy = 2 * r + hr;
            unsigned base = (unsigned)(hy * 36 + oxq) * 32;
            unsigned ad[6];
#pragma unroll
            for (int j = 0; j < 6; j++) ad[j] = swz(base + j * 32);

#pragma unroll
            for (int ck = 0; ck < 2; ck++) {
                const ull* wA = c_pack.w2[pset][4 * g + 2 * ck];
                const ull* wB = wA + 9;     // next pair, contiguous
                ull A[6], B[6];
#pragma unroll
                for (int j = 0; j < 6; j++) {
                    // swz(x+16) == swz(x) ^ 16 for x % 32 == 0  (XOR, not +)
                    ulonglong2 v =
                        *(const ulonglong2*)(sHb + (ad[j] ^ (ck * 16)));
                    A[j] = v.x; B[j] = v.y;
                }
                if (hr <= 2) {            // contributes to row 2r (dy = hr)
#pragma unroll
                    for (int t = 0; t < 3; t++) {
                        ull wa = wA[hr * 3 + t], wb = wB[hr * 3 + t];
                        a00 = fma2(wa, A[t],     a00);
                        a01 = fma2(wa, A[t + 1], a01);
                        a02 = fma2(wa, A[t + 2], a02);
                        a03 = fma2(wa, A[t + 3], a03);
                        a00 = fma2(wb, B[t],     a00);
                        a01 = fma2(wb, B[t + 1], a01);
                        a02 = fma2(wb, B[t + 2], a02);
                        a03 = fma2(wb, B[t + 3], a03);
                    }
                }
                if (hr >= 1) {            // contributes to row 2r+1 (dy = hr-1)
#pragma unroll
                    for (int t = 0; t < 3; t++) {
                        ull wa = wA[(hr - 1) * 3 + t], wb = wB[(hr - 1) * 3 + t];
                        a10 = fma2(wa, A[t],     a10);
                        a11 = fma2(wa, A[t + 1], a11);
                        a12 = fma2(wa, A[t + 2], a12);
                        a13 = fma2(wa, A[t + 3], a13);
                        a10 = fma2(wb, B[t],     a10);
                        a11 = fma2(wb, B[t + 1], a11);
                        a12 = fma2(wb, B[t + 2], a12);
                        a13 = fma2(wb, B[t + 3], a13);
                    }
                }
            }
        }
        if (g == 0) __syncthreads();   // before next pass overwrites sH
    }

    // --- epilogue: O = S + sign*acc, float4 per row ---
    float2 f00 = unpack2(a00), f01 = unpack2(a01),
           f02 = unpack2(a02), f03 = unpack2(a03);
    float2 f10 = unpack2(a10), f11 = unpack2(a11),
           f12 = unpack2(a12), f13 = unpack2(a13);

    const float* Si = S + (size_t)img * h * w;
    float* Oi = O + (size_t)img * h * w;
    size_t p0 = (size_t)(by + 2 * r) * w + bx + oxq;
    size_t p1 = p0 + w;

    float4 s0 = *(const float4*)(Si + p0);
    float4 s1 = *(const float4*)(Si + p1);
    float4 o0, o1;
    o0.x = s0.x + sign * (f00.x + f00.y);
    o0.y = s0.y + sign * (f01.x + f01.y);
    o0.z = s0.z + sign * (f02.x + f02.y);
    o0.w = s0.w + sign * (f03.x + f03.y);
    o1.x = s1.x + sign * (f10.x + f10.y);
    o1.y = s1.y + sign * (f11.x + f11.y);
    o1.z = s1.z + sign * (f12.x + f12.y);
    o1.w = s1.w + sign * (f13.x + f13.y);
    *(float4*)(Oi + p0) = o0;
    *(float4*)(Oi + p1) = o1;
}

// ---------------------------------------------------------------------------
// Kernel 3: transpose + even/odd split (L and H via grid.z).
// ---------------------------------------------------------------------------
__global__ void transpose_split_kernel(const float* __restrict__ Lsrc,
                                       const float* __restrict__ Hsrc,
                                       float* __restrict__ LLd, float* __restrict__ HLd,
                                       float* __restrict__ LHd, float* __restrict__ HHd,
                                       int h, int w)
{
    __shared__ float tile[32][65];
    int z = blockIdx.z;
    int which = z / NIMG, img = z - which * NIMG;
    const float* T = which ? Hsrc : Lsrc;
    float* E = which ? LHd : LLd;
    float* O = which ? HHd : HLd;

    const int c0 = blockIdx.x * 32;
    const int r0 = blockIdx.y * 32;
    const int tx = threadIdx.x, ty = threadIdx.y;

    const float* Ti = T + (size_t)img * h * w;
#pragma unroll
    for (int k = 0; k < 4; k++) {
        int cc = ty + 8 * k;
        const float* row = Ti + (size_t)(c0 + cc) * w + 2 * r0;
        tile[cc][tx]      = row[tx];
        tile[cc][tx + 32] = row[tx + 32];
    }
    __syncthreads();

    size_t imgo = (size_t)img * (w / 2) * h;
#pragma unroll
    for (int k = 0; k < 4; k++) {
        int rr = ty + 8 * k;
        size_t o = imgo + (size_t)(r0 + rr) * h + c0 + tx;
        E[o] = tile[tx][2 * rr];
        O[o] = tile[tx][2 * rr + 1];
    }
}

// ---------------------------------------------------------------------------
// Kernel 4: gather. out[b, q*3+c, i, j] = Q_q[c*8+b, j, i]
// ---------------------------------------------------------------------------
__global__ void gather_kernel(const float* __restrict__ LL, const float* __restrict__ HL,
                              const float* __restrict__ LH, const float* __restrict__ HH,
                              float* __restrict__ out)
{
    __shared__ float tile[32][33];
    int z = blockIdx.z;
    int q = z / NIMG, img = z - q * NIMG;
    const float* Q = (q == 0) ? LL : (q == 1) ? HL : (q == 2) ? LH : HH;
    int b = img & 7, cch = img >> 3;
    int chan = q * 3 + cch;

    int i0 = blockIdx.x * 32, j0 = blockIdx.y * 32;
    int tx = threadIdx.x, ty = threadIdx.y;

    const float* Qi = Q + (size_t)img * 65536;
#pragma unroll
    for (int k = 0; k < 4; k++) {
        int jj = ty + 8 * k;
        tile[jj][tx] = Qi[(size_t)(j0 + jj) * 256 + i0 + tx];
    }
    __syncthreads();

    float* o = out + ((size_t)b * 12 + chan) * 65536;
#pragma unroll
    for (int k = 0; k < 4; k++) {
        int ii = ty + 8 * k;
        o[(size_t)(i0 + ii) * 256 + j0 + tx] = tile[tx][ii];
    }
}

// ---------------------------------------------------------------------------
extern "C" void kernel_launch(void* const* d_in, const int* in_sizes, int n_in,
                              void* d_out, int out_size)
{
    const float* x   = (const float*)d_in[0];
    const float* Wp1 = (const float*)d_in[1];
    const float* bp1 = (const float*)d_in[2];
    const float* Wp2 = (const float*)d_in[3];
    const float* bp2 = (const float*)d_in[4];
    const float* Wu1 = (const float*)d_in[5];
    const float* bu1 = (const float*)d_in[6];
    const float* Wu2 = (const float*)d_in[7];
    const float* bu2 = (const float*)d_in[8];
    float* out = (float*)d_out;

    // opt in to >48KB dynamic SMEM (idempotent)
    cudaFuncSetAttribute(subnet_lift_kernel,
                         cudaFuncAttributeMaxDynamicSharedMemorySize, SMEM_TOTAL);

    // pack weights on device, then stage into __constant__
    prep_kernel<<<1, 256>>>(Wp1, bp1, Wp2, bp2, Wu1, bu1, Wu2, bu2);
    PackedW* pg;
    cudaGetSymbolAddress((void**)&pg, g_pack);
    cudaMemcpyToSymbolAsync(c_pack, pg, sizeof(PackedW), 0, cudaMemcpyDeviceToDevice);

    float *pL, *pH, *pLL, *pHL, *pLH, *pHH;
    cudaGetSymbolAddress((void**)&pL,  g_L);
    cudaGetSymbolAddress((void**)&pH,  g_H);
    cudaGetSymbolAddress((void**)&pLL, g_LL);
    cudaGetSymbolAddress((void**)&pHL, g_HL);
    cudaGetSymbolAddress((void**)&pLH, g_LH);
    cudaGetSymbolAddress((void**)&pHH, g_HH);

    // 1) rgb->yuv + row split
    yuv_split_kernel<<<dim3(1024, 8), 256>>>(x, pL, pH);

    // 2) lift 1 (rows), 24 x 256 x 512 ; tiles 32w x 64h
    dim3 g1(512 / 32, 256 / 64, NIMG);
    subnet_lift_kernel<<<g1, 256, SMEM_TOTAL>>>(pL, pH, pH, pL, pH, pH,
                                                0, -1.f, 256, 512);
    subnet_lift_kernel<<<g1, 256, SMEM_TOTAL>>>(pH, pL, pL, pH, pL, pL,
                                                1, +1.f, 256, 512);

    // 3) transpose + column split
    dim3 gt(256 / 32, 256 / 32, 2 * NIMG);
    transpose_split_kernel<<<gt, dim3(32, 8)>>>(pL, pH, pLL, pHL, pLH, pHH, 256, 512);

    // 4) lift 2 (L branch) and lift 3 (H branch) fused per step, grid.z = 48
    dim3 g2(256 / 32, 256 / 64, 2 * NIMG);
    subnet_lift_kernel<<<g2, 256, SMEM_TOTAL>>>(pLL, pHL, pHL, pLH, pHH, pHH,
                                                0, -1.f, 256, 256);
    subnet_lift_kernel<<<g2, 256, SMEM_TOTAL>>>(pHL, pLL, pLL, pHH, pLH, pLH,
                                                1, +1.f, 256, 256);

    // 5) transpose back + batch2channel + concat -> out [8,12,256,256]
    gather_kernel<<<dim3(8, 8, 96), dim3(32, 8)>>>(pLL, pHL, pLH, pHH, out);
}